// round 6
// baseline (speedup 1.0000x reference)
#include <cuda_runtime.h>
#include <cuda_bf16.h>
#include <math.h>

#define NB   256
#define NT   128
#define VOC  42
#define LATD 200
#define UU   512
#define PP   3
#define BT   (NB*NT)
#define G4U  2048
#define DOM_BLOCKS 32   // blocks per barrier domain (32 u-blocks per b-group)

// ---------------- device scratch ----------------
__device__ __nv_bfloat16 g_bufA[(size_t)BT*UU];
__device__ __nv_bfloat16 g_bufB[(size_t)BT*UU];
__device__ float g_Z[(size_t)BT*G4U];              // gate-interleaved: [b,t,u,4]
__device__ float g_hf32[(size_t)BT*UU];            // fp32 hseq (for CE)
__device__ __nv_bfloat16 g_wt[(size_t)G4U*UU];
__device__ unsigned g_rkt[(size_t)G4U*UU];
__device__ float g_h0[NB*UU];
__device__ float g_h1[NB*UU];
__device__ float g_c[NB*UU];
__device__ float g_mean[NB*LATD];
__device__ float g_ls[NB*LATD];
__device__ float g_zlat[NB*LATD];
__device__ float g_acc[2];
__device__ unsigned g_bar[4];

// ---------------- helpers ----------------
__device__ __forceinline__ unsigned f2tf32(float x) {
    unsigned r;
    asm("cvt.rna.tf32.f32 %0, %1;" : "=r"(r) : "f"(x));
    return r;
}
__device__ __forceinline__ void mma_tf32(float c[4], const unsigned a[4], const unsigned b[2]) {
    asm volatile(
        "mma.sync.aligned.m16n8k8.row.col.f32.tf32.tf32.f32 "
        "{%0,%1,%2,%3}, {%4,%5,%6,%7}, {%8,%9}, {%0,%1,%2,%3};\n"
        : "+f"(c[0]), "+f"(c[1]), "+f"(c[2]), "+f"(c[3])
        : "r"(a[0]), "r"(a[1]), "r"(a[2]), "r"(a[3]), "r"(b[0]), "r"(b[1]));
}
__device__ __forceinline__ void mma_bf16(float c[4], const unsigned a[4], const unsigned b[2]) {
    asm volatile(
        "mma.sync.aligned.m16n8k16.row.col.f32.bf16.bf16.f32 "
        "{%0,%1,%2,%3}, {%4,%5,%6,%7}, {%8,%9}, {%0,%1,%2,%3};\n"
        : "+f"(c[0]), "+f"(c[1]), "+f"(c[2]), "+f"(c[3])
        : "r"(a[0]), "r"(a[1]), "r"(a[2]), "r"(a[3]), "r"(b[0]), "r"(b[1]));
}
__device__ __forceinline__ float sigm(float x) { return 1.f / (1.f + expf(-x)); }

__device__ __forceinline__ void cp16(void* s, const void* g) {
    unsigned sa = (unsigned)__cvta_generic_to_shared(s);
    asm volatile("cp.async.cg.shared.global [%0], [%1], 16;\n" :: "r"(sa), "l"(g));
}
#define CP_COMMIT() asm volatile("cp.async.commit_group;\n")
#define CP_WAIT(n)  asm volatile("cp.async.wait_group %0;\n" :: "n"(n))

// ---------------- utility kernels ----------------
__global__ void k_zero(float* p, int n) {
    int i = blockIdx.x * blockDim.x + threadIdx.x;
    if (i < n) p[i] = 0.f;
}
__global__ void k_reset_bar(unsigned* b) {
    if (threadIdx.x < 4) b[threadIdx.x] = 0u;
}

__global__ void k_build_enc(const int* __restrict__ X, const float* __restrict__ emb,
                            const float* __restrict__ C, __nv_bfloat16* __restrict__ out) {
    int bt = blockIdx.x;
    int b = bt / NT;
    __nv_bfloat16* row = out + (size_t)bt * UU;
    int x = X[bt];
    for (int i = threadIdx.x; i < UU; i += blockDim.x) {
        float v = 0.f;
        if (i < LATD) v = emb[x * LATD + i];
        else if (i < LATD + PP) v = C[b * PP + (i - LATD)];
        row[i] = __float2bfloat16_rn(v);
    }
}
__global__ void k_build_dec(const int* __restrict__ X, const float* __restrict__ emb,
                            const float* __restrict__ C, const float* __restrict__ zl,
                            __nv_bfloat16* __restrict__ out) {
    int bt = blockIdx.x;
    int b = bt / NT;
    __nv_bfloat16* row = out + (size_t)bt * UU;
    int x = X[bt];
    for (int i = threadIdx.x; i < UU; i += blockDim.x) {
        float v = 0.f;
        if (i < LATD) v = zl[b * LATD + i];
        else if (i < 2 * LATD) v = emb[x * LATD + (i - LATD)];
        else if (i < 2 * LATD + PP) v = C[b * PP + (i - 2 * LATD)];
        row[i] = __float2bfloat16_rn(v);
    }
}

__global__ void k_convT(const float* __restrict__ W, int K, __nv_bfloat16* __restrict__ Wt) {
    __shared__ float tile[32][33];
    int nb0 = blockIdx.x * 32;
    int kb0 = blockIdx.y * 32;
    for (int i = threadIdx.x; i < 1024; i += blockDim.x) {
        int r = i >> 5, c = i & 31;
        tile[r][c] = (kb0 + r < K) ? W[(size_t)(kb0 + r) * G4U + nb0 + c] : 0.f;
    }
    __syncthreads();
    for (int i = threadIdx.x; i < 1024; i += blockDim.x) {
        int r = i >> 5, c = i & 31;
        Wt[(size_t)(nb0 + r) * UU + kb0 + c] = __float2bfloat16_rn(tile[c][r]);
    }
}

__global__ void k_convT_tf32(const float* __restrict__ W, unsigned* __restrict__ Wt) {
    __shared__ float tile[32][33];
    int nb0 = blockIdx.x * 32;
    int kb0 = blockIdx.y * 32;
    for (int i = threadIdx.x; i < 1024; i += blockDim.x) {
        int r = i >> 5, c = i & 31;
        tile[r][c] = W[(size_t)(kb0 + r) * G4U + nb0 + c];
    }
    __syncthreads();
    for (int i = threadIdx.x; i < 1024; i += blockDim.x) {
        int r = i >> 5, c = i & 31;
        Wt[(size_t)(nb0 + r) * UU + kb0 + c] = f2tf32(tile[c][r]);
    }
}

// ---------------- big GEMM, cp.async double-buffered ----------------
// Output written gate-interleaved: Co[row*2048 + u*4 + gate], gate=col>>9, u=col&511.
#define GS (128 * 72)
#define SMEM_GEMM (4 * GS * 2)

__global__ __launch_bounds__(256) void k_gemm_bf16(
    const __nv_bfloat16* __restrict__ A, const __nv_bfloat16* __restrict__ Wt,
    const float* __restrict__ bias, float* __restrict__ Co) {
    extern __shared__ __nv_bfloat16 gsm[];
    int tid = threadIdx.x;
    int wid = tid >> 5, lane = tid & 31;
    int wm = wid >> 1, wn = wid & 1;
    int lq = lane >> 2, lr = lane & 3;
    int row0 = blockIdx.y * 128, col0 = blockIdx.x * 128;

    float c[2][8][4];
#pragma unroll
    for (int mt = 0; mt < 2; mt++)
#pragma unroll
        for (int nt = 0; nt < 8; nt++)
#pragma unroll
            for (int j = 0; j < 4; j++) c[mt][nt][j] = 0.f;

    auto load_chunk = [&](int buf, int kk) {
        __nv_bfloat16* As_ = gsm + buf * 2 * GS;
        __nv_bfloat16* Bs_ = As_ + GS;
#pragma unroll
        for (int j = 0; j < 4; j++) {
            int i = tid + j * 256;
            int r = i >> 3, c8 = (i & 7) * 8;
            cp16(&As_[r * 72 + c8], &A[(size_t)(row0 + r) * UU + kk + c8]);
            cp16(&Bs_[r * 72 + c8], &Wt[(size_t)(col0 + r) * UU + kk + c8]);
        }
    };

    load_chunk(0, 0);
    CP_COMMIT();

    for (int kc = 0; kc < 8; kc++) {
        if (kc < 7) {
            load_chunk((kc + 1) & 1, (kc + 1) * 64);
            CP_COMMIT();
            CP_WAIT(1);
        } else {
            CP_WAIT(0);
        }
        __syncthreads();
        const __nv_bfloat16* As_ = gsm + (kc & 1) * 2 * GS;
        const __nv_bfloat16* Bs_ = As_ + GS;
#pragma unroll
        for (int ks = 0; ks < 4; ks++) {
            int kb = ks * 16;
            unsigned af[2][4];
#pragma unroll
            for (int mt = 0; mt < 2; mt++) {
                int mb = wm * 32 + mt * 16;
                af[mt][0] = *(const unsigned*)&As_[(mb + lq) * 72 + kb + 2 * lr];
                af[mt][1] = *(const unsigned*)&As_[(mb + lq + 8) * 72 + kb + 2 * lr];
                af[mt][2] = *(const unsigned*)&As_[(mb + lq) * 72 + kb + 8 + 2 * lr];
                af[mt][3] = *(const unsigned*)&As_[(mb + lq + 8) * 72 + kb + 8 + 2 * lr];
            }
#pragma unroll
            for (int nt = 0; nt < 8; nt++) {
                int nb = wn * 64 + nt * 8;
                unsigned bf[2];
                bf[0] = *(const unsigned*)&Bs_[(nb + lq) * 72 + kb + 2 * lr];
                bf[1] = *(const unsigned*)&Bs_[(nb + lq) * 72 + kb + 8 + 2 * lr];
#pragma unroll
                for (int mt = 0; mt < 2; mt++) mma_bf16(c[mt][nt], af[mt], bf);
            }
        }
        __syncthreads();
    }
#pragma unroll
    for (int mt = 0; mt < 2; mt++) {
        size_t rb = (size_t)(row0 + wm * 32 + mt * 16 + lq);
#pragma unroll
        for (int nt = 0; nt < 8; nt++) {
            int cb = col0 + wn * 64 + nt * 8 + 2 * lr;
            int gate = cb >> 9, u = cb & 511;
            int off = (u << 2) | gate;          // cb+1: same gate, u+1 -> off+4
            float b0 = bias[cb], b1 = bias[cb + 1];
            Co[rb * G4U + off]           = c[mt][nt][0] + b0;
            Co[rb * G4U + off + 4]       = c[mt][nt][1] + b1;
            Co[(rb + 8) * G4U + off]     = c[mt][nt][2] + b0;
            Co[(rb + 8) * G4U + off + 4] = c[mt][nt][3] + b1;
        }
    }
}

// ---------------- persistent tf32 scan ----------------
#define SC_WS 516
#define SC_HS 132
#define SMEM_SCAN (64*SC_WS*4 + 2*64*SC_HS*4 + 64*68*4 + 64*16*4)

__global__ __launch_bounds__(256) void k_scan_tf32(
    const float* __restrict__ Z, const unsigned* __restrict__ rkt,
    float* __restrict__ h0buf, float* __restrict__ h1buf,
    __nv_bfloat16* __restrict__ hseq, float* __restrict__ hseq32,
    float* __restrict__ cfin, volatile unsigned* bar) {
    extern __shared__ char smraw[];
    unsigned* Wsm = (unsigned*)smraw;
    float* hsm0 = (float*)(smraw + 64 * SC_WS * 4);
    float* hsm1 = hsm0 + 64 * SC_HS;
    float* zsm = (float*)(smraw + 64 * SC_WS * 4 + 2 * 64 * SC_HS * 4);
    float* csm = zsm + 64 * 68;

    int tid = threadIdx.x;
    int wid = tid >> 5, lane = tid & 31;
    int wm = wid >> 1, wn = wid & 1;
    int lq = lane >> 2, lr = lane & 3;
    int u0 = blockIdx.x * 16;
    int b0 = blockIdx.y * 64;
    volatile unsigned* mybar = bar + blockIdx.y;   // per-b-group domain

    for (int i = tid; i < 64 * 128; i += 256) {
        int nl = i >> 7, kq = (i & 127) * 4;
        int n = (nl >> 4) * 512 + u0 + (nl & 15);
        *(uint4*)&Wsm[nl * SC_WS + kq] = *(const uint4*)&rkt[(size_t)n * UU + kq];
    }
    for (int i = tid; i < 1024; i += 256) csm[i] = 0.f;
    __syncthreads();

    for (int t = 0; t < NT; t++) {
        // ---- prefetch Z (gate-interleaved, one LDG.128 per rep) ----
        float4 zreg[4];
#pragma unroll
        for (int rep = 0; rep < 4; rep++) {
            int e = rep * 256 + tid;
            int bl = e >> 4, ulx = e & 15;
            zreg[rep] = __ldg((const float4*)&Z[(((size_t)(b0 + bl) * NT + t) << 11) +
                                                ((u0 + ulx) << 2)]);
        }

        float acc[4][4];
#pragma unroll
        for (int nt = 0; nt < 4; nt++)
#pragma unroll
            for (int j = 0; j < 4; j++) acc[nt][j] = 0.f;

        if (t > 0) {
            if (tid == 0) {
                unsigned target = (unsigned)t * DOM_BLOCKS;
                while (*mybar < target) {}
            }
            __syncthreads();
            const float* hprev = ((t - 1) & 1) ? h1buf : h0buf;

#pragma unroll
            for (int j = 0; j < 8; j++) {
                int i = tid + j * 256;
                int r = i >> 5, cq = (i & 31) * 4;
                cp16(&hsm0[r * SC_HS + cq], &hprev[(size_t)(b0 + r) * UU + cq]);
            }
            CP_COMMIT();

            int mb = wm * 16;
            for (int kc = 0; kc < 4; kc++) {
                float* cur = (kc & 1) ? hsm1 : hsm0;
                float* nxt = (kc & 1) ? hsm0 : hsm1;
                if (kc < 3) {
                    int kk = (kc + 1) * 128;
#pragma unroll
                    for (int j = 0; j < 8; j++) {
                        int i = tid + j * 256;
                        int r = i >> 5, cq = (i & 31) * 4;
                        cp16(&nxt[r * SC_HS + cq], &hprev[(size_t)(b0 + r) * UU + kk + cq]);
                    }
                    CP_COMMIT();
                    CP_WAIT(1);
                } else {
                    CP_WAIT(0);
                }
                __syncthreads();
                const unsigned* cu = (const unsigned*)cur;
#pragma unroll
                for (int ks = 0; ks < 16; ks++) {
                    int kb = ks * 8;
                    unsigned af[4];
                    af[0] = cu[(mb + lq) * SC_HS + kb + lr];
                    af[1] = cu[(mb + lq + 8) * SC_HS + kb + lr];
                    af[2] = cu[(mb + lq) * SC_HS + kb + lr + 4];
                    af[3] = cu[(mb + lq + 8) * SC_HS + kb + lr + 4];
#pragma unroll
                    for (int nt = 0; nt < 4; nt++) {
                        int nb = wn * 32 + nt * 8;
                        unsigned bf[2];
                        bf[0] = Wsm[(nb + lq) * SC_WS + kc * 128 + kb + lr];
                        bf[1] = Wsm[(nb + lq) * SC_WS + kc * 128 + kb + lr + 4];
                        mma_tf32(acc[nt], af, bf);
                    }
                }
                __syncthreads();
            }
        }

        // scatter gate preacts to zsm[64][68]
        {
            int rb = wm * 16 + lq;
#pragma unroll
            for (int nt = 0; nt < 4; nt++) {
                int cb = wn * 32 + nt * 8 + 2 * lr;
                zsm[rb * 68 + cb]           = acc[nt][0];
                zsm[rb * 68 + cb + 1]       = acc[nt][1];
                zsm[(rb + 8) * 68 + cb]     = acc[nt][2];
                zsm[(rb + 8) * 68 + cb + 1] = acc[nt][3];
            }
        }
        __syncthreads();

        // LSTM update
        float* hnext = (t & 1) ? h1buf : h0buf;
#pragma unroll
        for (int rep = 0; rep < 4; rep++) {
            int e = rep * 256 + tid;
            int bl = e >> 4, ulx = e & 15;
            int b = b0 + bl, u = u0 + ulx;
            float zi = zsm[bl * 68 + ulx]      + zreg[rep].x;
            float zf = zsm[bl * 68 + 16 + ulx] + zreg[rep].y;
            float zg = zsm[bl * 68 + 32 + ulx] + zreg[rep].z;
            float zo = zsm[bl * 68 + 48 + ulx] + zreg[rep].w;
            float co = csm[bl * 16 + ulx];
            float c2 = sigm(zf) * co + sigm(zi) * tanhf(zg);
            float h2 = sigm(zo) * tanhf(c2);
            csm[bl * 16 + ulx] = c2;
            // round to tf32 at write: recurrence sees rna-rounded h (matches R4 numerics)
            __stcg(&hnext[(size_t)b * UU + u], __uint_as_float(f2tf32(h2)));
            size_t so = ((size_t)b * NT + t) * UU + u;
            hseq[so] = __float2bfloat16_rn(h2);
            hseq32[so] = h2;
        }

        if (t < NT - 1) {
            __threadfence();
            __syncthreads();
            if (tid == 0) atomicAdd((unsigned*)mybar, 1u);
        }
    }
#pragma unroll
    for (int rep = 0; rep < 4; rep++) {
        int e = rep * 256 + tid;
        int bl = e >> 4, ulx = e & 15;
        cfin[(b0 + bl) * UU + u0 + ulx] = csm[bl * 16 + ulx];
    }
}

// ---------------- mean / log_sigma / reparameterize ----------------
__global__ void k_mean_ls(const float* __restrict__ cst,
                          const float* __restrict__ Wm, const float* __restrict__ bm,
                          const float* __restrict__ Ws, const float* __restrict__ bs,
                          const float* __restrict__ eps,
                          float* __restrict__ mo, float* __restrict__ lo, float* __restrict__ zo) {
    int idx = blockIdx.x * blockDim.x + threadIdx.x;
    if (idx >= NB * LATD) return;
    int b = idx / LATD, l = idx % LATD;
    const float* cr = cst + b * UU;
    float m = bm[l], s = bs[l];
    for (int k = 0; k < UU; k++) {
        float cv = cr[k];
        m += cv * Wm[k * LATD + l];
        s += cv * Ws[k * LATD + l];
    }
    mo[idx] = m;
    lo[idx] = s;
    zo[idx] = m + expf(0.5f * s) * eps[idx];
}

__global__ void k_latent(const float* __restrict__ mo, const float* __restrict__ lo,
                         float* __restrict__ acc) {
    __shared__ float sdata[256];
    int idx = blockIdx.x * blockDim.x + threadIdx.x;
    float v = 0.f;
    if (idx < NB * LATD) {
        float m = mo[idx], s = lo[idx];
        v = 1.f + s - m * m - expf(s);
    }
    sdata[threadIdx.x] = v;
    __syncthreads();
    for (int o = 128; o > 0; o >>= 1) {
        if (threadIdx.x < o) sdata[threadIdx.x] += sdata[threadIdx.x + o];
        __syncthreads();
    }
    if (threadIdx.x == 0) atomicAdd(acc + 1, sdata[0]);
}

// ---------------- fused logits + log-softmax + masked CE (fp32 h) ----------------
__global__ void k_ce(const float* __restrict__ H, const float* __restrict__ Wo,
                     const float* __restrict__ bo, const int* __restrict__ Y,
                     const int* __restrict__ L, float* __restrict__ acc) {
    __shared__ float hs[8][UU];
    int row0 = blockIdx.x * 8;
    for (int i = threadIdx.x; i < 8 * UU; i += 256) {
        int r = i >> 9, k = i & 511;
        hs[r][k] = H[(size_t)(row0 + r) * UU + k];
    }
    __syncthreads();
    int w = threadIdx.x >> 5, lane = threadIdx.x & 31;
    int row = row0 + w;
    int b = row / NT, t = row % NT;

    float d0 = 0.f, d1 = 0.f;
    bool has1 = (lane + 32) < VOC;
    for (int k = 0; k < UU; k++) {
        float hv = hs[w][k];
        d0 += hv * Wo[k * VOC + lane];
        if (has1) d1 += hv * Wo[k * VOC + lane + 32];
    }
    float p0 = d0 + bo[lane];
    float p1 = has1 ? (d1 + bo[lane + 32]) : -1e30f;
    float m = fmaxf(p0, p1);
#pragma unroll
    for (int o = 16; o; o >>= 1) m = fmaxf(m, __shfl_xor_sync(0xffffffffu, m, o));
    float e = expf(p0 - m) + (has1 ? expf(p1 - m) : 0.f);
#pragma unroll
    for (int o = 16; o; o >>= 1) e += __shfl_xor_sync(0xffffffffu, e, o);
    float lse = logf(e) + m;
    int y = Y[row];
    float py = __shfl_sync(0xffffffffu, (y < 32) ? p0 : p1, y & 31);
    if (lane == 0) {
        float wt = (t < L[b]) ? 1.f : 0.f;
        atomicAdd(acc, (lse - py) * wt);
    }
}

__global__ void k_final(const float* __restrict__ acc, float* __restrict__ out, int out_size) {
    if (threadIdx.x == 0) {
        float recon = acc[0] / (float)BT;
        float lat = -0.5f * acc[1] / (float)(NB * LATD);
        if (out_size > 0) out[0] = recon + lat;
        if (out_size > 1) out[1] = recon;
        if (out_size > 2) out[2] = lat;
    }
}

// ---------------- host driver ----------------
extern "C" void kernel_launch(void* const* d_in, const int* in_sizes, int n_in,
                              void* d_out, int out_size) {
    const int*   X       = (const int*)d_in[0];
    const int*   Y       = (const int*)d_in[1];
    const float* C       = (const float*)d_in[2];
    const int*   L       = (const int*)d_in[3];
    const float* eps     = (const float*)d_in[4];
    const float* emb_enc = (const float*)d_in[5];
    const float* emb_dec = (const float*)d_in[6];
    const float* enc_k[3]  = {(const float*)d_in[7],  (const float*)d_in[10], (const float*)d_in[13]};
    const float* enc_rk[3] = {(const float*)d_in[8],  (const float*)d_in[11], (const float*)d_in[14]};
    const float* enc_b[3]  = {(const float*)d_in[9],  (const float*)d_in[12], (const float*)d_in[15]};
    const float* dec_k[3]  = {(const float*)d_in[16], (const float*)d_in[19], (const float*)d_in[22]};
    const float* dec_rk[3] = {(const float*)d_in[17], (const float*)d_in[20], (const float*)d_in[23]};
    const float* dec_b[3]  = {(const float*)d_in[18], (const float*)d_in[21], (const float*)d_in[24]};
    const float* Wm = (const float*)d_in[25];
    const float* bm = (const float*)d_in[26];
    const float* Ws = (const float*)d_in[27];
    const float* bs = (const float*)d_in[28];
    const float* Wo = (const float*)d_in[29];
    const float* bo = (const float*)d_in[30];

    __nv_bfloat16 *bufA, *bufB, *wt;
    unsigned *rkt, *bar;
    float *Zb, *cst, *mo, *lo, *zl, *acc, *h0, *h1, *hf32;
    cudaGetSymbolAddress((void**)&bufA, g_bufA);
    cudaGetSymbolAddress((void**)&bufB, g_bufB);
    cudaGetSymbolAddress((void**)&wt,   g_wt);
    cudaGetSymbolAddress((void**)&rkt,  g_rkt);
    cudaGetSymbolAddress((void**)&Zb,   g_Z);
    cudaGetSymbolAddress((void**)&cst,  g_c);
    cudaGetSymbolAddress((void**)&mo,   g_mean);
    cudaGetSymbolAddress((void**)&lo,   g_ls);
    cudaGetSymbolAddress((void**)&zl,   g_zlat);
    cudaGetSymbolAddress((void**)&acc,  g_acc);
    cudaGetSymbolAddress((void**)&h0,   g_h0);
    cudaGetSymbolAddress((void**)&h1,   g_h1);
    cudaGetSymbolAddress((void**)&hf32, g_hf32);
    cudaGetSymbolAddress((void**)&bar,  g_bar);

    static int smem_set = 0;
    if (!smem_set) {
        cudaFuncSetAttribute(k_scan_tf32, cudaFuncAttributeMaxDynamicSharedMemorySize, SMEM_SCAN);
        cudaFuncSetAttribute(k_gemm_bf16, cudaFuncAttributeMaxDynamicSharedMemorySize, SMEM_GEMM);
        smem_set = 1;
    }

    k_zero<<<1, 64>>>(acc, 2);

    dim3 gemm_grid(G4U / 128, BT / 128);
    dim3 conv_grid(64, 16);
    dim3 scan_grid(32, 4);

    const int encKs[3] = {LATD + PP, UU, UU};
    const int decKs[3] = {2 * LATD + PP, UU, UU};

    // ======== encoder ========
    k_build_enc<<<BT, 256>>>(X, emb_enc, C, bufA);
    {
        __nv_bfloat16* inb = bufA;
        __nv_bfloat16* outb = bufB;
        for (int l = 0; l < 3; l++) {
            k_convT<<<conv_grid, 256>>>(enc_k[l], encKs[l], wt);
            k_gemm_bf16<<<gemm_grid, 256, SMEM_GEMM>>>(inb, wt, enc_b[l], Zb);
            k_convT_tf32<<<conv_grid, 256>>>(enc_rk[l], rkt);
            k_reset_bar<<<1, 32>>>(bar);
            k_scan_tf32<<<scan_grid, 256, SMEM_SCAN>>>(Zb, rkt, h0, h1, outb, hf32, cst, bar);
            __nv_bfloat16* tmp = inb; inb = outb; outb = tmp;
        }
    }
    k_mean_ls<<<(NB * LATD + 255) / 256, 256>>>(cst, Wm, bm, Ws, bs, eps, mo, lo, zl);
    k_latent<<<(NB * LATD + 255) / 256, 256>>>(mo, lo, acc);

    // ======== decoder ========
    k_build_dec<<<BT, 256>>>(X, emb_dec, C, zl, bufA);
    {
        __nv_bfloat16* inb = bufA;
        __nv_bfloat16* outb = bufB;
        for (int l = 0; l < 3; l++) {
            k_convT<<<conv_grid, 256>>>(dec_k[l], decKs[l], wt);
            k_gemm_bf16<<<gemm_grid, 256, SMEM_GEMM>>>(inb, wt, dec_b[l], Zb);
            k_convT_tf32<<<conv_grid, 256>>>(dec_rk[l], rkt);
            k_reset_bar<<<1, 32>>>(bar);
            k_scan_tf32<<<scan_grid, 256, SMEM_SCAN>>>(Zb, rkt, h0, h1, outb, hf32, cst, bar);
            __nv_bfloat16* tmp = inb; inb = outb; outb = tmp;
        }
    }

    // ======== losses (CE reads fp32 hseq of last decoder layer) ========
    k_ce<<<BT / 8, 256>>>(hf32, Wo, bo, Y, L, acc);
    k_final<<<1, 32>>>(acc, (float*)d_out, out_size);
}

// round 7
// speedup vs baseline: 1.0009x; 1.0009x over previous
#include <cuda_runtime.h>
#include <cuda_bf16.h>
#include <math.h>

#define NB   256
#define NT   128
#define VOC  42
#define LATD 200
#define UU   512
#define PP   3
#define BT   (NB*NT)
#define G4U  2048
#define DOM_BLOCKS 32   // blocks per barrier domain (32 u-blocks per b-group)

// ---------------- device scratch ----------------
__device__ __nv_bfloat16 g_bufA[(size_t)BT*UU];
__device__ __nv_bfloat16 g_bufB[(size_t)BT*UU];
__device__ float g_Z[(size_t)BT*G4U];              // gate-interleaved: [b,t,u,4]
__device__ float g_hf32[(size_t)BT*UU];            // fp32 hseq (for CE)
__device__ __nv_bfloat16 g_wt[(size_t)G4U*UU];
__device__ unsigned g_rkt[(size_t)G4U*UU];
__device__ float g_h0[NB*UU];
__device__ float g_h1[NB*UU];
__device__ float g_c[NB*UU];
__device__ float g_mean[NB*LATD];
__device__ float g_ls[NB*LATD];
__device__ float g_zlat[NB*LATD];
__device__ float g_acc[2];
__device__ unsigned g_bar[4];

// ---------------- helpers ----------------
__device__ __forceinline__ unsigned f2tf32(float x) {
    unsigned r;
    asm("cvt.rna.tf32.f32 %0, %1;" : "=r"(r) : "f"(x));
    return r;
}
__device__ __forceinline__ void mma_tf32(float c[4], const unsigned a[4], const unsigned b[2]) {
    asm volatile(
        "mma.sync.aligned.m16n8k8.row.col.f32.tf32.tf32.f32 "
        "{%0,%1,%2,%3}, {%4,%5,%6,%7}, {%8,%9}, {%0,%1,%2,%3};\n"
        : "+f"(c[0]), "+f"(c[1]), "+f"(c[2]), "+f"(c[3])
        : "r"(a[0]), "r"(a[1]), "r"(a[2]), "r"(a[3]), "r"(b[0]), "r"(b[1]));
}
__device__ __forceinline__ void mma_bf16(float c[4], const unsigned a[4], const unsigned b[2]) {
    asm volatile(
        "mma.sync.aligned.m16n8k16.row.col.f32.bf16.bf16.f32 "
        "{%0,%1,%2,%3}, {%4,%5,%6,%7}, {%8,%9}, {%0,%1,%2,%3};\n"
        : "+f"(c[0]), "+f"(c[1]), "+f"(c[2]), "+f"(c[3])
        : "r"(a[0]), "r"(a[1]), "r"(a[2]), "r"(a[3]), "r"(b[0]), "r"(b[1]));
}
__device__ __forceinline__ float sigm(float x) { return 1.f / (1.f + expf(-x)); }

__device__ __forceinline__ void cp16(void* s, const void* g) {
    unsigned sa = (unsigned)__cvta_generic_to_shared(s);
    asm volatile("cp.async.cg.shared.global [%0], [%1], 16;\n" :: "r"(sa), "l"(g));
}
#define CP_COMMIT() asm volatile("cp.async.commit_group;\n")
#define CP_WAIT(n)  asm volatile("cp.async.wait_group %0;\n" :: "n"(n))

// ---------------- utility kernels ----------------
__global__ void k_zero(float* p, int n) {
    int i = blockIdx.x * blockDim.x + threadIdx.x;
    if (i < n) p[i] = 0.f;
}
__global__ void k_reset_bar(unsigned* b) {
    if (threadIdx.x < 4) b[threadIdx.x] = 0u;
}

__global__ void k_build_enc(const int* __restrict__ X, const float* __restrict__ emb,
                            const float* __restrict__ C, __nv_bfloat16* __restrict__ out) {
    int bt = blockIdx.x;
    int b = bt / NT;
    __nv_bfloat16* row = out + (size_t)bt * UU;
    int x = X[bt];
    for (int i = threadIdx.x; i < UU; i += blockDim.x) {
        float v = 0.f;
        if (i < LATD) v = emb[x * LATD + i];
        else if (i < LATD + PP) v = C[b * PP + (i - LATD)];
        row[i] = __float2bfloat16_rn(v);
    }
}
__global__ void k_build_dec(const int* __restrict__ X, const float* __restrict__ emb,
                            const float* __restrict__ C, const float* __restrict__ zl,
                            __nv_bfloat16* __restrict__ out) {
    int bt = blockIdx.x;
    int b = bt / NT;
    __nv_bfloat16* row = out + (size_t)bt * UU;
    int x = X[bt];
    for (int i = threadIdx.x; i < UU; i += blockDim.x) {
        float v = 0.f;
        if (i < LATD) v = zl[b * LATD + i];
        else if (i < 2 * LATD) v = emb[x * LATD + (i - LATD)];
        else if (i < 2 * LATD + PP) v = C[b * PP + (i - 2 * LATD)];
        row[i] = __float2bfloat16_rn(v);
    }
}

__global__ void k_convT(const float* __restrict__ W, int K, __nv_bfloat16* __restrict__ Wt) {
    __shared__ float tile[32][33];
    int nb0 = blockIdx.x * 32;
    int kb0 = blockIdx.y * 32;
    for (int i = threadIdx.x; i < 1024; i += blockDim.x) {
        int r = i >> 5, c = i & 31;
        tile[r][c] = (kb0 + r < K) ? W[(size_t)(kb0 + r) * G4U + nb0 + c] : 0.f;
    }
    __syncthreads();
    for (int i = threadIdx.x; i < 1024; i += blockDim.x) {
        int r = i >> 5, c = i & 31;
        Wt[(size_t)(nb0 + r) * UU + kb0 + c] = __float2bfloat16_rn(tile[c][r]);
    }
}

__global__ void k_convT_tf32(const float* __restrict__ W, unsigned* __restrict__ Wt) {
    __shared__ float tile[32][33];
    int nb0 = blockIdx.x * 32;
    int kb0 = blockIdx.y * 32;
    for (int i = threadIdx.x; i < 1024; i += blockDim.x) {
        int r = i >> 5, c = i & 31;
        tile[r][c] = W[(size_t)(kb0 + r) * G4U + nb0 + c];
    }
    __syncthreads();
    for (int i = threadIdx.x; i < 1024; i += blockDim.x) {
        int r = i >> 5, c = i & 31;
        Wt[(size_t)(nb0 + r) * UU + kb0 + c] = f2tf32(tile[c][r]);
    }
}

// ---------------- big GEMM, cp.async double-buffered ----------------
// Output written gate-interleaved: Co[row*2048 + u*4 + gate], gate=col>>9, u=col&511.
#define GS (128 * 72)
#define SMEM_GEMM (4 * GS * 2)

__global__ __launch_bounds__(256) void k_gemm_bf16(
    const __nv_bfloat16* __restrict__ A, const __nv_bfloat16* __restrict__ Wt,
    const float* __restrict__ bias, float* __restrict__ Co) {
    extern __shared__ __nv_bfloat16 gsm[];
    int tid = threadIdx.x;
    int wid = tid >> 5, lane = tid & 31;
    int wm = wid >> 1, wn = wid & 1;
    int lq = lane >> 2, lr = lane & 3;
    int row0 = blockIdx.y * 128, col0 = blockIdx.x * 128;

    float c[2][8][4];
#pragma unroll
    for (int mt = 0; mt < 2; mt++)
#pragma unroll
        for (int nt = 0; nt < 8; nt++)
#pragma unroll
            for (int j = 0; j < 4; j++) c[mt][nt][j] = 0.f;

    auto load_chunk = [&](int buf, int kk) {
        __nv_bfloat16* As_ = gsm + buf * 2 * GS;
        __nv_bfloat16* Bs_ = As_ + GS;
#pragma unroll
        for (int j = 0; j < 4; j++) {
            int i = tid + j * 256;
            int r = i >> 3, c8 = (i & 7) * 8;
            cp16(&As_[r * 72 + c8], &A[(size_t)(row0 + r) * UU + kk + c8]);
            cp16(&Bs_[r * 72 + c8], &Wt[(size_t)(col0 + r) * UU + kk + c8]);
        }
    };

    load_chunk(0, 0);
    CP_COMMIT();

    for (int kc = 0; kc < 8; kc++) {
        if (kc < 7) {
            load_chunk((kc + 1) & 1, (kc + 1) * 64);
            CP_COMMIT();
            CP_WAIT(1);
        } else {
            CP_WAIT(0);
        }
        __syncthreads();
        const __nv_bfloat16* As_ = gsm + (kc & 1) * 2 * GS;
        const __nv_bfloat16* Bs_ = As_ + GS;
#pragma unroll
        for (int ks = 0; ks < 4; ks++) {
            int kb = ks * 16;
            unsigned af[2][4];
#pragma unroll
            for (int mt = 0; mt < 2; mt++) {
                int mb = wm * 32 + mt * 16;
                af[mt][0] = *(const unsigned*)&As_[(mb + lq) * 72 + kb + 2 * lr];
                af[mt][1] = *(const unsigned*)&As_[(mb + lq + 8) * 72 + kb + 2 * lr];
                af[mt][2] = *(const unsigned*)&As_[(mb + lq) * 72 + kb + 8 + 2 * lr];
                af[mt][3] = *(const unsigned*)&As_[(mb + lq + 8) * 72 + kb + 8 + 2 * lr];
            }
#pragma unroll
            for (int nt = 0; nt < 8; nt++) {
                int nb = wn * 64 + nt * 8;
                unsigned bf[2];
                bf[0] = *(const unsigned*)&Bs_[(nb + lq) * 72 + kb + 2 * lr];
                bf[1] = *(const unsigned*)&Bs_[(nb + lq) * 72 + kb + 8 + 2 * lr];
#pragma unroll
                for (int mt = 0; mt < 2; mt++) mma_bf16(c[mt][nt], af[mt], bf);
            }
        }
        __syncthreads();
    }
#pragma unroll
    for (int mt = 0; mt < 2; mt++) {
        size_t rb = (size_t)(row0 + wm * 32 + mt * 16 + lq);
#pragma unroll
        for (int nt = 0; nt < 8; nt++) {
            int cb = col0 + wn * 64 + nt * 8 + 2 * lr;
            int gate = cb >> 9, u = cb & 511;
            int off = (u << 2) | gate;          // cb+1: same gate, u+1 -> off+4
            float b0 = bias[cb], b1 = bias[cb + 1];
            Co[rb * G4U + off]           = c[mt][nt][0] + b0;
            Co[rb * G4U + off + 4]       = c[mt][nt][1] + b1;
            Co[(rb + 8) * G4U + off]     = c[mt][nt][2] + b0;
            Co[(rb + 8) * G4U + off + 4] = c[mt][nt][3] + b1;
        }
    }
}

// ---------------- persistent tf32 scan ----------------
#define SC_WS 516
#define SC_HS 132
#define SMEM_SCAN (64*SC_WS*4 + 2*64*SC_HS*4 + 64*68*4 + 64*16*4)

__global__ __launch_bounds__(256) void k_scan_tf32(
    const float* __restrict__ Z, const unsigned* __restrict__ rkt,
    float* __restrict__ h0buf, float* __restrict__ h1buf,
    __nv_bfloat16* __restrict__ hseq, float* __restrict__ hseq32,
    float* __restrict__ cfin, volatile unsigned* bar) {
    extern __shared__ char smraw[];
    unsigned* Wsm = (unsigned*)smraw;
    float* hsm0 = (float*)(smraw + 64 * SC_WS * 4);
    float* hsm1 = hsm0 + 64 * SC_HS;
    float* zsm = (float*)(smraw + 64 * SC_WS * 4 + 2 * 64 * SC_HS * 4);
    float* csm = zsm + 64 * 68;

    int tid = threadIdx.x;
    int wid = tid >> 5, lane = tid & 31;
    int wm = wid >> 1, wn = wid & 1;
    int lq = lane >> 2, lr = lane & 3;
    int u0 = blockIdx.x * 16;
    int b0 = blockIdx.y * 64;
    volatile unsigned* mybar = bar + blockIdx.y;   // per-b-group domain

    for (int i = tid; i < 64 * 128; i += 256) {
        int nl = i >> 7, kq = (i & 127) * 4;
        int n = (nl >> 4) * 512 + u0 + (nl & 15);
        *(uint4*)&Wsm[nl * SC_WS + kq] = *(const uint4*)&rkt[(size_t)n * UU + kq];
    }
    for (int i = tid; i < 1024; i += 256) csm[i] = 0.f;
    __syncthreads();

    for (int t = 0; t < NT; t++) {
        // ---- prefetch Z (gate-interleaved, one LDG.128 per rep) ----
        float4 zreg[4];
#pragma unroll
        for (int rep = 0; rep < 4; rep++) {
            int e = rep * 256 + tid;
            int bl = e >> 4, ulx = e & 15;
            zreg[rep] = __ldg((const float4*)&Z[(((size_t)(b0 + bl) * NT + t) << 11) +
                                                ((u0 + ulx) << 2)]);
        }

        float acc[4][4];
#pragma unroll
        for (int nt = 0; nt < 4; nt++)
#pragma unroll
            for (int j = 0; j < 4; j++) acc[nt][j] = 0.f;

        if (t > 0) {
            if (tid == 0) {
                unsigned target = (unsigned)t * DOM_BLOCKS;
                while (*mybar < target) {}
            }
            __syncthreads();
            const float* hprev = ((t - 1) & 1) ? h1buf : h0buf;

#pragma unroll
            for (int j = 0; j < 8; j++) {
                int i = tid + j * 256;
                int r = i >> 5, cq = (i & 31) * 4;
                cp16(&hsm0[r * SC_HS + cq], &hprev[(size_t)(b0 + r) * UU + cq]);
            }
            CP_COMMIT();

            int mb = wm * 16;
            for (int kc = 0; kc < 4; kc++) {
                float* cur = (kc & 1) ? hsm1 : hsm0;
                float* nxt = (kc & 1) ? hsm0 : hsm1;
                if (kc < 3) {
                    int kk = (kc + 1) * 128;
#pragma unroll
                    for (int j = 0; j < 8; j++) {
                        int i = tid + j * 256;
                        int r = i >> 5, cq = (i & 31) * 4;
                        cp16(&nxt[r * SC_HS + cq], &hprev[(size_t)(b0 + r) * UU + kk + cq]);
                    }
                    CP_COMMIT();
                    CP_WAIT(1);
                } else {
                    CP_WAIT(0);
                }
                __syncthreads();
                const unsigned* cu = (const unsigned*)cur;
#pragma unroll
                for (int ks = 0; ks < 16; ks++) {
                    int kb = ks * 8;
                    unsigned af[4];
                    af[0] = cu[(mb + lq) * SC_HS + kb + lr];
                    af[1] = cu[(mb + lq + 8) * SC_HS + kb + lr];
                    af[2] = cu[(mb + lq) * SC_HS + kb + lr + 4];
                    af[3] = cu[(mb + lq + 8) * SC_HS + kb + lr + 4];
#pragma unroll
                    for (int nt = 0; nt < 4; nt++) {
                        int nb = wn * 32 + nt * 8;
                        unsigned bf[2];
                        bf[0] = Wsm[(nb + lq) * SC_WS + kc * 128 + kb + lr];
                        bf[1] = Wsm[(nb + lq) * SC_WS + kc * 128 + kb + lr + 4];
                        mma_tf32(acc[nt], af, bf);
                    }
                }
                __syncthreads();
            }
        }

        // scatter gate preacts to zsm[64][68]
        {
            int rb = wm * 16 + lq;
#pragma unroll
            for (int nt = 0; nt < 4; nt++) {
                int cb = wn * 32 + nt * 8 + 2 * lr;
                zsm[rb * 68 + cb]           = acc[nt][0];
                zsm[rb * 68 + cb + 1]       = acc[nt][1];
                zsm[(rb + 8) * 68 + cb]     = acc[nt][2];
                zsm[(rb + 8) * 68 + cb + 1] = acc[nt][3];
            }
        }
        __syncthreads();

        // LSTM update
        float* hnext = (t & 1) ? h1buf : h0buf;
#pragma unroll
        for (int rep = 0; rep < 4; rep++) {
            int e = rep * 256 + tid;
            int bl = e >> 4, ulx = e & 15;
            int b = b0 + bl, u = u0 + ulx;
            float zi = zsm[bl * 68 + ulx]      + zreg[rep].x;
            float zf = zsm[bl * 68 + 16 + ulx] + zreg[rep].y;
            float zg = zsm[bl * 68 + 32 + ulx] + zreg[rep].z;
            float zo = zsm[bl * 68 + 48 + ulx] + zreg[rep].w;
            float co = csm[bl * 16 + ulx];
            float c2 = sigm(zf) * co + sigm(zi) * tanhf(zg);
            float h2 = sigm(zo) * tanhf(c2);
            csm[bl * 16 + ulx] = c2;
            // round to tf32 at write: recurrence sees rna-rounded h (matches R4 numerics)
            __stcg(&hnext[(size_t)b * UU + u], __uint_as_float(f2tf32(h2)));
            size_t so = ((size_t)b * NT + t) * UU + u;
            hseq[so] = __float2bfloat16_rn(h2);
            hseq32[so] = h2;
        }

        if (t < NT - 1) {
            __threadfence();
            __syncthreads();
            if (tid == 0) atomicAdd((unsigned*)mybar, 1u);
        }
    }
#pragma unroll
    for (int rep = 0; rep < 4; rep++) {
        int e = rep * 256 + tid;
        int bl = e >> 4, ulx = e & 15;
        cfin[(b0 + bl) * UU + u0 + ulx] = csm[bl * 16 + ulx];
    }
}

// ---------------- mean / log_sigma / reparameterize ----------------
__global__ void k_mean_ls(const float* __restrict__ cst,
                          const float* __restrict__ Wm, const float* __restrict__ bm,
                          const float* __restrict__ Ws, const float* __restrict__ bs,
                          const float* __restrict__ eps,
                          float* __restrict__ mo, float* __restrict__ lo, float* __restrict__ zo) {
    int idx = blockIdx.x * blockDim.x + threadIdx.x;
    if (idx >= NB * LATD) return;
    int b = idx / LATD, l = idx % LATD;
    const float* cr = cst + b * UU;
    float m = bm[l], s = bs[l];
    for (int k = 0; k < UU; k++) {
        float cv = cr[k];
        m += cv * Wm[k * LATD + l];
        s += cv * Ws[k * LATD + l];
    }
    mo[idx] = m;
    lo[idx] = s;
    zo[idx] = m + expf(0.5f * s) * eps[idx];
}

__global__ void k_latent(const float* __restrict__ mo, const float* __restrict__ lo,
                         float* __restrict__ acc) {
    __shared__ float sdata[256];
    int idx = blockIdx.x * blockDim.x + threadIdx.x;
    float v = 0.f;
    if (idx < NB * LATD) {
        float m = mo[idx], s = lo[idx];
        v = 1.f + s - m * m - expf(s);
    }
    sdata[threadIdx.x] = v;
    __syncthreads();
    for (int o = 128; o > 0; o >>= 1) {
        if (threadIdx.x < o) sdata[threadIdx.x] += sdata[threadIdx.x + o];
        __syncthreads();
    }
    if (threadIdx.x == 0) atomicAdd(acc + 1, sdata[0]);
}

// ---------------- fused logits + log-softmax + masked CE (fp32 h) ----------------
__global__ void k_ce(const float* __restrict__ H, const float* __restrict__ Wo,
                     const float* __restrict__ bo, const int* __restrict__ Y,
                     const int* __restrict__ L, float* __restrict__ acc) {
    __shared__ float hs[8][UU];
    int row0 = blockIdx.x * 8;
    for (int i = threadIdx.x; i < 8 * UU; i += 256) {
        int r = i >> 9, k = i & 511;
        hs[r][k] = H[(size_t)(row0 + r) * UU + k];
    }
    __syncthreads();
    int w = threadIdx.x >> 5, lane = threadIdx.x & 31;
    int row = row0 + w;
    int b = row / NT, t = row % NT;

    float d0 = 0.f, d1 = 0.f;
    bool has1 = (lane + 32) < VOC;
    for (int k = 0; k < UU; k++) {
        float hv = hs[w][k];
        d0 += hv * Wo[k * VOC + lane];
        if (has1) d1 += hv * Wo[k * VOC + lane + 32];
    }
    float p0 = d0 + bo[lane];
    float p1 = has1 ? (d1 + bo[lane + 32]) : -1e30f;
    float m = fmaxf(p0, p1);
#pragma unroll
    for (int o = 16; o; o >>= 1) m = fmaxf(m, __shfl_xor_sync(0xffffffffu, m, o));
    float e = expf(p0 - m) + (has1 ? expf(p1 - m) : 0.f);
#pragma unroll
    for (int o = 16; o; o >>= 1) e += __shfl_xor_sync(0xffffffffu, e, o);
    float lse = logf(e) + m;
    int y = Y[row];
    float py = __shfl_sync(0xffffffffu, (y < 32) ? p0 : p1, y & 31);
    if (lane == 0) {
        float wt = (t < L[b]) ? 1.f : 0.f;
        atomicAdd(acc, (lse - py) * wt);
    }
}

__global__ void k_final(const float* __restrict__ acc, float* __restrict__ out, int out_size) {
    if (threadIdx.x == 0) {
        float recon = acc[0] / (float)BT;
        float lat = -0.5f * acc[1] / (float)(NB * LATD);
        if (out_size > 0) out[0] = recon + lat;
        if (out_size > 1) out[1] = recon;
        if (out_size > 2) out[2] = lat;
    }
}

// ---------------- host driver ----------------
extern "C" void kernel_launch(void* const* d_in, const int* in_sizes, int n_in,
                              void* d_out, int out_size) {
    const int*   X       = (const int*)d_in[0];
    const int*   Y       = (const int*)d_in[1];
    const float* C       = (const float*)d_in[2];
    const int*   L       = (const int*)d_in[3];
    const float* eps     = (const float*)d_in[4];
    const float* emb_enc = (const float*)d_in[5];
    const float* emb_dec = (const float*)d_in[6];
    const float* enc_k[3]  = {(const float*)d_in[7],  (const float*)d_in[10], (const float*)d_in[13]};
    const float* enc_rk[3] = {(const float*)d_in[8],  (const float*)d_in[11], (const float*)d_in[14]};
    const float* enc_b[3]  = {(const float*)d_in[9],  (const float*)d_in[12], (const float*)d_in[15]};
    const float* dec_k[3]  = {(const float*)d_in[16], (const float*)d_in[19], (const float*)d_in[22]};
    const float* dec_rk[3] = {(const float*)d_in[17], (const float*)d_in[20], (const float*)d_in[23]};
    const float* dec_b[3]  = {(const float*)d_in[18], (const float*)d_in[21], (const float*)d_in[24]};
    const float* Wm = (const float*)d_in[25];
    const float* bm = (const float*)d_in[26];
    const float* Ws = (const float*)d_in[27];
    const float* bs = (const float*)d_in[28];
    const float* Wo = (const float*)d_in[29];
    const float* bo = (const float*)d_in[30];

    __nv_bfloat16 *bufA, *bufB, *wt;
    unsigned *rkt, *bar;
    float *Zb, *cst, *mo, *lo, *zl, *acc, *h0, *h1, *hf32;
    cudaGetSymbolAddress((void**)&bufA, g_bufA);
    cudaGetSymbolAddress((void**)&bufB, g_bufB);
    cudaGetSymbolAddress((void**)&wt,   g_wt);
    cudaGetSymbolAddress((void**)&rkt,  g_rkt);
    cudaGetSymbolAddress((void**)&Zb,   g_Z);
    cudaGetSymbolAddress((void**)&cst,  g_c);
    cudaGetSymbolAddress((void**)&mo,   g_mean);
    cudaGetSymbolAddress((void**)&lo,   g_ls);
    cudaGetSymbolAddress((void**)&zl,   g_zlat);
    cudaGetSymbolAddress((void**)&acc,  g_acc);
    cudaGetSymbolAddress((void**)&h0,   g_h0);
    cudaGetSymbolAddress((void**)&h1,   g_h1);
    cudaGetSymbolAddress((void**)&hf32, g_hf32);
    cudaGetSymbolAddress((void**)&bar,  g_bar);

    static int smem_set = 0;
    if (!smem_set) {
        cudaFuncSetAttribute(k_scan_tf32, cudaFuncAttributeMaxDynamicSharedMemorySize, SMEM_SCAN);
        cudaFuncSetAttribute(k_gemm_bf16, cudaFuncAttributeMaxDynamicSharedMemorySize, SMEM_GEMM);
        smem_set = 1;
    }

    k_zero<<<1, 64>>>(acc, 2);

    dim3 gemm_grid(G4U / 128, BT / 128);
    dim3 conv_grid(64, 16);
    dim3 scan_grid(32, 4);

    const int encKs[3] = {LATD + PP, UU, UU};
    const int decKs[3] = {2 * LATD + PP, UU, UU};

    // ======== encoder ========
    k_build_enc<<<BT, 256>>>(X, emb_enc, C, bufA);
    {
        __nv_bfloat16* inb = bufA;
        __nv_bfloat16* outb = bufB;
        for (int l = 0; l < 3; l++) {
            k_convT<<<conv_grid, 256>>>(enc_k[l], encKs[l], wt);
            k_gemm_bf16<<<gemm_grid, 256, SMEM_GEMM>>>(inb, wt, enc_b[l], Zb);
            k_convT_tf32<<<conv_grid, 256>>>(enc_rk[l], rkt);
            k_reset_bar<<<1, 32>>>(bar);
            k_scan_tf32<<<scan_grid, 256, SMEM_SCAN>>>(Zb, rkt, h0, h1, outb, hf32, cst, bar);
            __nv_bfloat16* tmp = inb; inb = outb; outb = tmp;
        }
    }
    k_mean_ls<<<(NB * LATD + 255) / 256, 256>>>(cst, Wm, bm, Ws, bs, eps, mo, lo, zl);
    k_latent<<<(NB * LATD + 255) / 256, 256>>>(mo, lo, acc);

    // ======== decoder ========
    k_build_dec<<<BT, 256>>>(X, emb_dec, C, zl, bufA);
    {
        __nv_bfloat16* inb = bufA;
        __nv_bfloat16* outb = bufB;
        for (int l = 0; l < 3; l++) {
            k_convT<<<conv_grid, 256>>>(dec_k[l], decKs[l], wt);
            k_gemm_bf16<<<gemm_grid, 256, SMEM_GEMM>>>(inb, wt, dec_b[l], Zb);
            k_convT_tf32<<<conv_grid, 256>>>(dec_rk[l], rkt);
            k_reset_bar<<<1, 32>>>(bar);
            k_scan_tf32<<<scan_grid, 256, SMEM_SCAN>>>(Zb, rkt, h0, h1, outb, hf32, cst, bar);
            __nv_bfloat16* tmp = inb; inb = outb; outb = tmp;
        }
    }

    // ======== losses (CE reads fp32 hseq of last decoder layer) ========
    k_ce<<<BT / 8, 256>>>(hf32, Wo, bo, Y, L, acc);
    k_final<<<1, 32>>>(acc, (float*)d_out, out_size);
}

// round 8
// speedup vs baseline: 1.1070x; 1.1060x over previous
#include <cuda_runtime.h>
#include <cuda_bf16.h>
#include <math.h>

#define NB   256
#define NT   128
#define VOC  42
#define LATD 200
#define UU   512
#define PP   3
#define BT   (NB*NT)
#define G4U  2048
#define DOM_BLOCKS 32

// ---------------- device scratch ----------------
__device__ __nv_bfloat16 g_bufA[(size_t)BT*UU];
__device__ __nv_bfloat16 g_bufB[(size_t)BT*UU];
__device__ float g_Z[(size_t)BT*G4U];              // gate-interleaved: [b,t,u,4]
__device__ float g_hf32[(size_t)BT*UU];            // fp32 hseq (for CE)
__device__ __nv_bfloat16 g_wt[(size_t)G4U*UU];     // permuted weight^T bf16
__device__ float g_pbias[G4U];                     // permuted bias
__device__ unsigned g_rkt[(size_t)G4U*UU];
__device__ float g_h0[NB*UU];
__device__ float g_h1[NB*UU];
__device__ float g_c[NB*UU];
__device__ float g_mean[NB*LATD];
__device__ float g_ls[NB*LATD];
__device__ float g_zlat[NB*LATD];
__device__ float g_acc[2];
__device__ unsigned g_bar[4];

// col permutation: gate-major (gate*512+u) -> interleaved (u*4+gate)
__device__ __forceinline__ int permcol(int n) { return ((n & 511) << 2) | (n >> 9); }

// ---------------- helpers ----------------
__device__ __forceinline__ unsigned f2tf32(float x) {
    unsigned r;
    asm("cvt.rna.tf32.f32 %0, %1;" : "=r"(r) : "f"(x));
    return r;
}
__device__ __forceinline__ void mma_tf32(float c[4], const unsigned a[4], const unsigned b[2]) {
    asm volatile(
        "mma.sync.aligned.m16n8k8.row.col.f32.tf32.tf32.f32 "
        "{%0,%1,%2,%3}, {%4,%5,%6,%7}, {%8,%9}, {%0,%1,%2,%3};\n"
        : "+f"(c[0]), "+f"(c[1]), "+f"(c[2]), "+f"(c[3])
        : "r"(a[0]), "r"(a[1]), "r"(a[2]), "r"(a[3]), "r"(b[0]), "r"(b[1]));
}
__device__ __forceinline__ void mma_bf16(float c[4], const unsigned a[4], const unsigned b[2]) {
    asm volatile(
        "mma.sync.aligned.m16n8k16.row.col.f32.bf16.bf16.f32 "
        "{%0,%1,%2,%3}, {%4,%5,%6,%7}, {%8,%9}, {%0,%1,%2,%3};\n"
        : "+f"(c[0]), "+f"(c[1]), "+f"(c[2]), "+f"(c[3])
        : "r"(a[0]), "r"(a[1]), "r"(a[2]), "r"(a[3]), "r"(b[0]), "r"(b[1]));
}
__device__ __forceinline__ float sigm(float x) { return 1.f / (1.f + expf(-x)); }

__device__ __forceinline__ void cp16(void* s, const void* g) {
    unsigned sa = (unsigned)__cvta_generic_to_shared(s);
    asm volatile("cp.async.cg.shared.global [%0], [%1], 16;\n" :: "r"(sa), "l"(g));
}
#define CP_COMMIT() asm volatile("cp.async.commit_group;\n")
#define CP_WAIT(n)  asm volatile("cp.async.wait_group %0;\n" :: "n"(n))

// ---------------- utility kernels ----------------
__global__ void k_zero(float* p, int n) {
    int i = blockIdx.x * blockDim.x + threadIdx.x;
    if (i < n) p[i] = 0.f;
}
__global__ void k_reset_bar(unsigned* b) {
    if (threadIdx.x < 4) b[threadIdx.x] = 0u;
}
__global__ void k_permbias(const float* __restrict__ bias, float* __restrict__ pb) {
    int n = blockIdx.x * blockDim.x + threadIdx.x;
    if (n < G4U) pb[permcol(n)] = bias[n];
}

__global__ void k_build_enc(const int* __restrict__ X, const float* __restrict__ emb,
                            const float* __restrict__ C, __nv_bfloat16* __restrict__ out) {
    int bt = blockIdx.x;
    int b = bt / NT;
    __nv_bfloat16* row = out + (size_t)bt * UU;
    int x = X[bt];
    for (int i = threadIdx.x; i < UU; i += blockDim.x) {
        float v = 0.f;
        if (i < LATD) v = emb[x * LATD + i];
        else if (i < LATD + PP) v = C[b * PP + (i - LATD)];
        row[i] = __float2bfloat16_rn(v);
    }
}
__global__ void k_build_dec(const int* __restrict__ X, const float* __restrict__ emb,
                            const float* __restrict__ C, const float* __restrict__ zl,
                            __nv_bfloat16* __restrict__ out) {
    int bt = blockIdx.x;
    int b = bt / NT;
    __nv_bfloat16* row = out + (size_t)bt * UU;
    int x = X[bt];
    for (int i = threadIdx.x; i < UU; i += blockDim.x) {
        float v = 0.f;
        if (i < LATD) v = zl[b * LATD + i];
        else if (i < 2 * LATD) v = emb[x * LATD + (i - LATD)];
        else if (i < 2 * LATD + PP) v = C[b * PP + (i - 2 * LATD)];
        row[i] = __float2bfloat16_rn(v);
    }
}

// transpose+convert with column permutation: W fp32 [K][2048] -> Wt bf16 [perm(n)][512]
__global__ void k_convT(const float* __restrict__ W, int K, __nv_bfloat16* __restrict__ Wt) {
    __shared__ float tile[32][33];
    int nb0 = blockIdx.x * 32;
    int kb0 = blockIdx.y * 32;
    for (int i = threadIdx.x; i < 1024; i += blockDim.x) {
        int r = i >> 5, c = i & 31;
        tile[r][c] = (kb0 + r < K) ? W[(size_t)(kb0 + r) * G4U + nb0 + c] : 0.f;
    }
    __syncthreads();
    for (int i = threadIdx.x; i < 1024; i += blockDim.x) {
        int r = i >> 5, c = i & 31;
        Wt[(size_t)permcol(nb0 + r) * UU + kb0 + c] = __float2bfloat16_rn(tile[c][r]);
    }
}

__global__ void k_convT_tf32(const float* __restrict__ W, unsigned* __restrict__ Wt) {
    __shared__ float tile[32][33];
    int nb0 = blockIdx.x * 32;
    int kb0 = blockIdx.y * 32;
    for (int i = threadIdx.x; i < 1024; i += blockDim.x) {
        int r = i >> 5, c = i & 31;
        tile[r][c] = W[(size_t)(kb0 + r) * G4U + nb0 + c];
    }
    __syncthreads();
    for (int i = threadIdx.x; i < 1024; i += blockDim.x) {
        int r = i >> 5, c = i & 31;
        Wt[(size_t)(nb0 + r) * UU + kb0 + c] = f2tf32(tile[c][r]);
    }
}

// ---------------- big GEMM, cp.async double-buffered (contiguous stores) ----------------
#define GS (128 * 72)
#define SMEM_GEMM (4 * GS * 2)

__global__ __launch_bounds__(256) void k_gemm_bf16(
    const __nv_bfloat16* __restrict__ A, const __nv_bfloat16* __restrict__ Wt,
    const float* __restrict__ bias, float* __restrict__ Co) {
    extern __shared__ __nv_bfloat16 gsm[];
    int tid = threadIdx.x;
    int wid = tid >> 5, lane = tid & 31;
    int wm = wid >> 1, wn = wid & 1;
    int lq = lane >> 2, lr = lane & 3;
    int row0 = blockIdx.y * 128, col0 = blockIdx.x * 128;

    float c[2][8][4];
#pragma unroll
    for (int mt = 0; mt < 2; mt++)
#pragma unroll
        for (int nt = 0; nt < 8; nt++)
#pragma unroll
            for (int j = 0; j < 4; j++) c[mt][nt][j] = 0.f;

    auto load_chunk = [&](int buf, int kk) {
        __nv_bfloat16* As_ = gsm + buf * 2 * GS;
        __nv_bfloat16* Bs_ = As_ + GS;
#pragma unroll
        for (int j = 0; j < 4; j++) {
            int i = tid + j * 256;
            int r = i >> 3, c8 = (i & 7) * 8;
            cp16(&As_[r * 72 + c8], &A[(size_t)(row0 + r) * UU + kk + c8]);
            cp16(&Bs_[r * 72 + c8], &Wt[(size_t)(col0 + r) * UU + kk + c8]);
        }
    };

    load_chunk(0, 0);
    CP_COMMIT();

    for (int kc = 0; kc < 8; kc++) {
        if (kc < 7) {
            load_chunk((kc + 1) & 1, (kc + 1) * 64);
            CP_COMMIT();
            CP_WAIT(1);
        } else {
            CP_WAIT(0);
        }
        __syncthreads();
        const __nv_bfloat16* As_ = gsm + (kc & 1) * 2 * GS;
        const __nv_bfloat16* Bs_ = As_ + GS;
#pragma unroll
        for (int ks = 0; ks < 4; ks++) {
            int kb = ks * 16;
            unsigned af[2][4];
#pragma unroll
            for (int mt = 0; mt < 2; mt++) {
                int mb = wm * 32 + mt * 16;
                af[mt][0] = *(const unsigned*)&As_[(mb + lq) * 72 + kb + 2 * lr];
                af[mt][1] = *(const unsigned*)&As_[(mb + lq + 8) * 72 + kb + 2 * lr];
                af[mt][2] = *(const unsigned*)&As_[(mb + lq) * 72 + kb + 8 + 2 * lr];
                af[mt][3] = *(const unsigned*)&As_[(mb + lq + 8) * 72 + kb + 8 + 2 * lr];
            }
#pragma unroll
            for (int nt = 0; nt < 8; nt++) {
                int nb = wn * 64 + nt * 8;
                unsigned bf[2];
                bf[0] = *(const unsigned*)&Bs_[(nb + lq) * 72 + kb + 2 * lr];
                bf[1] = *(const unsigned*)&Bs_[(nb + lq) * 72 + kb + 8 + 2 * lr];
#pragma unroll
                for (int mt = 0; mt < 2; mt++) mma_bf16(c[mt][nt], af[mt], bf);
            }
        }
        __syncthreads();
    }
#pragma unroll
    for (int mt = 0; mt < 2; mt++) {
        size_t rb = (size_t)(row0 + wm * 32 + mt * 16 + lq);
#pragma unroll
        for (int nt = 0; nt < 8; nt++) {
            int cb = col0 + wn * 64 + nt * 8 + 2 * lr;
            float b0 = bias[cb], b1 = bias[cb + 1];
            Co[rb * G4U + cb]           = c[mt][nt][0] + b0;
            Co[rb * G4U + cb + 1]       = c[mt][nt][1] + b1;
            Co[(rb + 8) * G4U + cb]     = c[mt][nt][2] + b0;
            Co[(rb + 8) * G4U + cb + 1] = c[mt][nt][3] + b1;
        }
    }
}

// ---------------- persistent tf32 scan ----------------
#define SC_WS 516
#define SC_HS 132
#define SMEM_SCAN (64*SC_WS*4 + 2*64*SC_HS*4 + 64*68*4 + 64*16*4)

__global__ __launch_bounds__(256) void k_scan_tf32(
    const float* __restrict__ Z, const unsigned* __restrict__ rkt,
    float* __restrict__ h0buf, float* __restrict__ h1buf,
    __nv_bfloat16* __restrict__ hseq, float* __restrict__ hseq32,
    float* __restrict__ cfin, volatile unsigned* bar) {
    extern __shared__ char smraw[];
    unsigned* Wsm = (unsigned*)smraw;
    float* hsm0 = (float*)(smraw + 64 * SC_WS * 4);
    float* hsm1 = hsm0 + 64 * SC_HS;
    float* zsm = (float*)(smraw + 64 * SC_WS * 4 + 2 * 64 * SC_HS * 4);
    float* csm = zsm + 64 * 68;

    int tid = threadIdx.x;
    int wid = tid >> 5, lane = tid & 31;
    int wm = wid >> 1, wn = wid & 1;
    int lq = lane >> 2, lr = lane & 3;
    int u0 = blockIdx.x * 16;
    int b0 = blockIdx.y * 64;
    volatile unsigned* mybar = bar + blockIdx.y;

    for (int i = tid; i < 64 * 128; i += 256) {
        int nl = i >> 7, kq = (i & 127) * 4;
        int n = (nl >> 4) * 512 + u0 + (nl & 15);
        *(uint4*)&Wsm[nl * SC_WS + kq] = *(const uint4*)&rkt[(size_t)n * UU + kq];
    }
    for (int i = tid; i < 1024; i += 256) csm[i] = 0.f;
    __syncthreads();

    for (int t = 0; t < NT; t++) {
        float4 zreg[4];
#pragma unroll
        for (int rep = 0; rep < 4; rep++) {
            int e = rep * 256 + tid;
            int bl = e >> 4, ulx = e & 15;
            zreg[rep] = __ldg((const float4*)&Z[(((size_t)(b0 + bl) * NT + t) << 11) +
                                                ((u0 + ulx) << 2)]);
        }

        float acc[4][4];
#pragma unroll
        for (int nt = 0; nt < 4; nt++)
#pragma unroll
            for (int j = 0; j < 4; j++) acc[nt][j] = 0.f;

        if (t > 0) {
            if (tid == 0) {
                unsigned target = (unsigned)t * DOM_BLOCKS;
                while (*mybar < target) {}
            }
            __syncthreads();
            const float* hprev = ((t - 1) & 1) ? h1buf : h0buf;

#pragma unroll
            for (int j = 0; j < 8; j++) {
                int i = tid + j * 256;
                int r = i >> 5, cq = (i & 31) * 4;
                cp16(&hsm0[r * SC_HS + cq], &hprev[(size_t)(b0 + r) * UU + cq]);
            }
            CP_COMMIT();

            int mb = wm * 16;
            for (int kc = 0; kc < 4; kc++) {
                float* cur = (kc & 1) ? hsm1 : hsm0;
                float* nxt = (kc & 1) ? hsm0 : hsm1;
                if (kc < 3) {
                    int kk = (kc + 1) * 128;
#pragma unroll
                    for (int j = 0; j < 8; j++) {
                        int i = tid + j * 256;
                        int r = i >> 5, cq = (i & 31) * 4;
                        cp16(&nxt[r * SC_HS + cq], &hprev[(size_t)(b0 + r) * UU + kk + cq]);
                    }
                    CP_COMMIT();
                    CP_WAIT(1);
                } else {
                    CP_WAIT(0);
                }
                __syncthreads();
                const unsigned* cu = (const unsigned*)cur;
#pragma unroll
                for (int ks = 0; ks < 16; ks++) {
                    int kb = ks * 8;
                    unsigned af[4];
                    af[0] = cu[(mb + lq) * SC_HS + kb + lr];
                    af[1] = cu[(mb + lq + 8) * SC_HS + kb + lr];
                    af[2] = cu[(mb + lq) * SC_HS + kb + lr + 4];
                    af[3] = cu[(mb + lq + 8) * SC_HS + kb + lr + 4];
#pragma unroll
                    for (int nt = 0; nt < 4; nt++) {
                        int nb = wn * 32 + nt * 8;
                        unsigned bf[2];
                        bf[0] = Wsm[(nb + lq) * SC_WS + kc * 128 + kb + lr];
                        bf[1] = Wsm[(nb + lq) * SC_WS + kc * 128 + kb + lr + 4];
                        mma_tf32(acc[nt], af, bf);
                    }
                }
                __syncthreads();
            }
        }

        {
            int rb = wm * 16 + lq;
#pragma unroll
            for (int nt = 0; nt < 4; nt++) {
                int cb = wn * 32 + nt * 8 + 2 * lr;
                zsm[rb * 68 + cb]           = acc[nt][0];
                zsm[rb * 68 + cb + 1]       = acc[nt][1];
                zsm[(rb + 8) * 68 + cb]     = acc[nt][2];
                zsm[(rb + 8) * 68 + cb + 1] = acc[nt][3];
            }
        }
        __syncthreads();

        float* hnext = (t & 1) ? h1buf : h0buf;
#pragma unroll
        for (int rep = 0; rep < 4; rep++) {
            int e = rep * 256 + tid;
            int bl = e >> 4, ulx = e & 15;
            int b = b0 + bl, u = u0 + ulx;
            float zi = zsm[bl * 68 + ulx]      + zreg[rep].x;
            float zf = zsm[bl * 68 + 16 + ulx] + zreg[rep].y;
            float zg = zsm[bl * 68 + 32 + ulx] + zreg[rep].z;
            float zo = zsm[bl * 68 + 48 + ulx] + zreg[rep].w;
            float co = csm[bl * 16 + ulx];
            float c2 = sigm(zf) * co + sigm(zi) * tanhf(zg);
            float h2 = sigm(zo) * tanhf(c2);
            csm[bl * 16 + ulx] = c2;
            __stcg(&hnext[(size_t)b * UU + u], __uint_as_float(f2tf32(h2)));
            size_t so = ((size_t)b * NT + t) * UU + u;
            hseq[so] = __float2bfloat16_rn(h2);
            hseq32[so] = h2;
        }

        if (t < NT - 1) {
            __threadfence();
            __syncthreads();
            if (tid == 0) atomicAdd((unsigned*)mybar, 1u);
        }
    }
#pragma unroll
    for (int rep = 0; rep < 4; rep++) {
        int e = rep * 256 + tid;
        int bl = e >> 4, ulx = e & 15;
        cfin[(b0 + bl) * UU + u0 + ulx] = csm[bl * 16 + ulx];
    }
}

// ---------------- mean / log_sigma / reparameterize ----------------
__global__ void k_mean_ls(const float* __restrict__ cst,
                          const float* __restrict__ Wm, const float* __restrict__ bm,
                          const float* __restrict__ Ws, const float* __restrict__ bs,
                          const float* __restrict__ eps,
                          float* __restrict__ mo, float* __restrict__ lo, float* __restrict__ zo) {
    int idx = blockIdx.x * blockDim.x + threadIdx.x;
    if (idx >= NB * LATD) return;
    int b = idx / LATD, l = idx % LATD;
    const float* cr = cst + b * UU;
    float m = bm[l], s = bs[l];
    for (int k = 0; k < UU; k++) {
        float cv = cr[k];
        m += cv * Wm[k * LATD + l];
        s += cv * Ws[k * LATD + l];
    }
    mo[idx] = m;
    lo[idx] = s;
    zo[idx] = m + expf(0.5f * s) * eps[idx];
}

__global__ void k_latent(const float* __restrict__ mo, const float* __restrict__ lo,
                         float* __restrict__ acc) {
    __shared__ float sdata[256];
    int idx = blockIdx.x * blockDim.x + threadIdx.x;
    float v = 0.f;
    if (idx < NB * LATD) {
        float m = mo[idx], s = lo[idx];
        v = 1.f + s - m * m - expf(s);
    }
    sdata[threadIdx.x] = v;
    __syncthreads();
    for (int o = 128; o > 0; o >>= 1) {
        if (threadIdx.x < o) sdata[threadIdx.x] += sdata[threadIdx.x + o];
        __syncthreads();
    }
    if (threadIdx.x == 0) atomicAdd(acc + 1, sdata[0]);
}

// ---------------- fused logits + log-softmax + masked CE (fp32 h) ----------------
__global__ void k_ce(const float* __restrict__ H, const float* __restrict__ Wo,
                     const float* __restrict__ bo, const int* __restrict__ Y,
                     const int* __restrict__ L, float* __restrict__ acc) {
    __shared__ float hs[8][UU];
    int row0 = blockIdx.x * 8;
    for (int i = threadIdx.x; i < 8 * UU; i += 256) {
        int r = i >> 9, k = i & 511;
        hs[r][k] = H[(size_t)(row0 + r) * UU + k];
    }
    __syncthreads();
    int w = threadIdx.x >> 5, lane = threadIdx.x & 31;
    int row = row0 + w;
    int b = row / NT, t = row % NT;

    float d0 = 0.f, d1 = 0.f;
    bool has1 = (lane + 32) < VOC;
    for (int k = 0; k < UU; k++) {
        float hv = hs[w][k];
        d0 += hv * Wo[k * VOC + lane];
        if (has1) d1 += hv * Wo[k * VOC + lane + 32];
    }
    float p0 = d0 + bo[lane];
    float p1 = has1 ? (d1 + bo[lane + 32]) : -1e30f;
    float m = fmaxf(p0, p1);
#pragma unroll
    for (int o = 16; o; o >>= 1) m = fmaxf(m, __shfl_xor_sync(0xffffffffu, m, o));
    float e = expf(p0 - m) + (has1 ? expf(p1 - m) : 0.f);
#pragma unroll
    for (int o = 16; o; o >>= 1) e += __shfl_xor_sync(0xffffffffu, e, o);
    float lse = logf(e) + m;
    int y = Y[row];
    float py = __shfl_sync(0xffffffffu, (y < 32) ? p0 : p1, y & 31);
    if (lane == 0) {
        float wt = (t < L[b]) ? 1.f : 0.f;
        atomicAdd(acc, (lse - py) * wt);
    }
}

__global__ void k_final(const float* __restrict__ acc, float* __restrict__ out, int out_size) {
    if (threadIdx.x == 0) {
        float recon = acc[0] / (float)BT;
        float lat = -0.5f * acc[1] / (float)(NB * LATD);
        if (out_size > 0) out[0] = recon + lat;
        if (out_size > 1) out[1] = recon;
        if (out_size > 2) out[2] = lat;
    }
}

// ---------------- host driver ----------------
extern "C" void kernel_launch(void* const* d_in, const int* in_sizes, int n_in,
                              void* d_out, int out_size) {
    const int*   X       = (const int*)d_in[0];
    const int*   Y       = (const int*)d_in[1];
    const float* C       = (const float*)d_in[2];
    const int*   L       = (const int*)d_in[3];
    const float* eps     = (const float*)d_in[4];
    const float* emb_enc = (const float*)d_in[5];
    const float* emb_dec = (const float*)d_in[6];
    const float* enc_k[3]  = {(const float*)d_in[7],  (const float*)d_in[10], (const float*)d_in[13]};
    const float* enc_rk[3] = {(const float*)d_in[8],  (const float*)d_in[11], (const float*)d_in[14]};
    const float* enc_b[3]  = {(const float*)d_in[9],  (const float*)d_in[12], (const float*)d_in[15]};
    const float* dec_k[3]  = {(const float*)d_in[16], (const float*)d_in[19], (const float*)d_in[22]};
    const float* dec_rk[3] = {(const float*)d_in[17], (const float*)d_in[20], (const float*)d_in[23]};
    const float* dec_b[3]  = {(const float*)d_in[18], (const float*)d_in[21], (const float*)d_in[24]};
    const float* Wm = (const float*)d_in[25];
    const float* bm = (const float*)d_in[26];
    const float* Ws = (const float*)d_in[27];
    const float* bs = (const float*)d_in[28];
    const float* Wo = (const float*)d_in[29];
    const float* bo = (const float*)d_in[30];

    __nv_bfloat16 *bufA, *bufB, *wt;
    unsigned *rkt, *bar;
    float *Zb, *cst, *mo, *lo, *zl, *acc, *h0, *h1, *hf32, *pb;
    cudaGetSymbolAddress((void**)&bufA, g_bufA);
    cudaGetSymbolAddress((void**)&bufB, g_bufB);
    cudaGetSymbolAddress((void**)&wt,   g_wt);
    cudaGetSymbolAddress((void**)&rkt,  g_rkt);
    cudaGetSymbolAddress((void**)&Zb,   g_Z);
    cudaGetSymbolAddress((void**)&cst,  g_c);
    cudaGetSymbolAddress((void**)&mo,   g_mean);
    cudaGetSymbolAddress((void**)&lo,   g_ls);
    cudaGetSymbolAddress((void**)&zl,   g_zlat);
    cudaGetSymbolAddress((void**)&acc,  g_acc);
    cudaGetSymbolAddress((void**)&h0,   g_h0);
    cudaGetSymbolAddress((void**)&h1,   g_h1);
    cudaGetSymbolAddress((void**)&hf32, g_hf32);
    cudaGetSymbolAddress((void**)&pb,   g_pbias);
    cudaGetSymbolAddress((void**)&bar,  g_bar);

    static int smem_set = 0;
    if (!smem_set) {
        cudaFuncSetAttribute(k_scan_tf32, cudaFuncAttributeMaxDynamicSharedMemorySize, SMEM_SCAN);
        cudaFuncSetAttribute(k_gemm_bf16, cudaFuncAttributeMaxDynamicSharedMemorySize, SMEM_GEMM);
        smem_set = 1;
    }

    k_zero<<<1, 64>>>(acc, 2);

    dim3 gemm_grid(G4U / 128, BT / 128);
    dim3 conv_grid(64, 16);
    dim3 scan_grid(32, 4);

    const int encKs[3] = {LATD + PP, UU, UU};
    const int decKs[3] = {2 * LATD + PP, UU, UU};

    // ======== encoder ========
    k_build_enc<<<BT, 256>>>(X, emb_enc, C, bufA);
    {
        __nv_bfloat16* inb = bufA;
        __nv_bfloat16* outb = bufB;
        for (int l = 0; l < 3; l++) {
            k_convT<<<conv_grid, 256>>>(enc_k[l], encKs[l], wt);
            k_permbias<<<8, 256>>>(enc_b[l], pb);
            k_gemm_bf16<<<gemm_grid, 256, SMEM_GEMM>>>(inb, wt, pb, Zb);
            k_convT_tf32<<<conv_grid, 256>>>(enc_rk[l], rkt);
            k_reset_bar<<<1, 32>>>(bar);
            k_scan_tf32<<<scan_grid, 256, SMEM_SCAN>>>(Zb, rkt, h0, h1, outb, hf32, cst, bar);
            __nv_bfloat16* tmp = inb; inb = outb; outb = tmp;
        }
    }
    k_mean_ls<<<(NB * LATD + 255) / 256, 256>>>(cst, Wm, bm, Ws, bs, eps, mo, lo, zl);
    k_latent<<<(NB * LATD + 255) / 256, 256>>>(mo, lo, acc);

    // ======== decoder ========
    k_build_dec<<<BT, 256>>>(X, emb_dec, C, zl, bufA);
    {
        __nv_bfloat16* inb = bufA;
        __nv_bfloat16* outb = bufB;
        for (int l = 0; l < 3; l++) {
            k_convT<<<conv_grid, 256>>>(dec_k[l], decKs[l], wt);
            k_permbias<<<8, 256>>>(dec_b[l], pb);
            k_gemm_bf16<<<gemm_grid, 256, SMEM_GEMM>>>(inb, wt, pb, Zb);
            k_convT_tf32<<<conv_grid, 256>>>(dec_rk[l], rkt);
            k_reset_bar<<<1, 32>>>(bar);
            k_scan_tf32<<<scan_grid, 256, SMEM_SCAN>>>(Zb, rkt, h0, h1, outb, hf32, cst, bar);
            __nv_bfloat16* tmp = inb; inb = outb; outb = tmp;
        }
    }

    // ======== losses ========
    k_ce<<<BT / 8, 256>>>(hf32, Wo, bo, Y, L, acc);
    k_final<<<1, 32>>>(acc, (float*)d_out, out_size);
}

// round 9
// speedup vs baseline: 1.1739x; 1.0605x over previous
#include <cuda_runtime.h>
#include <cuda_bf16.h>
#include <math.h>

#define NB   256
#define NT   128
#define VOC  42
#define LATD 200
#define UU   512
#define PP   3
#define BT   (NB*NT)
#define G4U  2048
#define DOM_BLOCKS 32

// ---------------- device scratch ----------------
__device__ __nv_bfloat16 g_bufA[(size_t)BT*UU];
__device__ __nv_bfloat16 g_bufB[(size_t)BT*UU];
__device__ float g_Z[(size_t)BT*G4U];              // gate-interleaved: [b,t,u,4]
__device__ float g_hf32[(size_t)BT*UU];            // fp32 hseq (for CE)
__device__ __nv_bfloat16 g_wt[(size_t)G4U*UU];     // permuted weight^T bf16
__device__ float g_pbias[G4U];                     // permuted bias
__device__ unsigned g_rkt[(size_t)G4U*UU];
__device__ float g_h0[NB*UU];
__device__ float g_h1[NB*UU];
__device__ float g_c[NB*UU];
__device__ float g_mean[NB*LATD];
__device__ float g_ls[NB*LATD];
__device__ float g_zlat[NB*LATD];
__device__ float g_acc[2];
__device__ unsigned g_bar[4];

__device__ __forceinline__ int permcol(int n) { return ((n & 511) << 2) | (n >> 9); }

// ---------------- helpers ----------------
__device__ __forceinline__ unsigned f2tf32(float x) {
    unsigned r;
    asm("cvt.rna.tf32.f32 %0, %1;" : "=r"(r) : "f"(x));
    return r;
}
__device__ __forceinline__ void mma_tf32(float c[4], const unsigned a[4], const unsigned b[2]) {
    asm volatile(
        "mma.sync.aligned.m16n8k8.row.col.f32.tf32.tf32.f32 "
        "{%0,%1,%2,%3}, {%4,%5,%6,%7}, {%8,%9}, {%0,%1,%2,%3};\n"
        : "+f"(c[0]), "+f"(c[1]), "+f"(c[2]), "+f"(c[3])
        : "r"(a[0]), "r"(a[1]), "r"(a[2]), "r"(a[3]), "r"(b[0]), "r"(b[1]));
}
__device__ __forceinline__ void mma_bf16(float c[4], const unsigned a[4], const unsigned b[2]) {
    asm volatile(
        "mma.sync.aligned.m16n8k16.row.col.f32.bf16.bf16.f32 "
        "{%0,%1,%2,%3}, {%4,%5,%6,%7}, {%8,%9}, {%0,%1,%2,%3};\n"
        : "+f"(c[0]), "+f"(c[1]), "+f"(c[2]), "+f"(c[3])
        : "r"(a[0]), "r"(a[1]), "r"(a[2]), "r"(a[3]), "r"(b[0]), "r"(b[1]));
}
__device__ __forceinline__ float sigm(float x) { return 1.f / (1.f + expf(-x)); }

__device__ __forceinline__ void cp16(void* s, const void* g) {
    unsigned sa = (unsigned)__cvta_generic_to_shared(s);
    asm volatile("cp.async.cg.shared.global [%0], [%1], 16;\n" :: "r"(sa), "l"(g));
}
#define CP_COMMIT() asm volatile("cp.async.commit_group;\n")
#define CP_WAIT(n)  asm volatile("cp.async.wait_group %0;\n" :: "n"(n))

// ---------------- utility kernels ----------------
__global__ void k_zero(float* p, int n) {
    int i = blockIdx.x * blockDim.x + threadIdx.x;
    if (i < n) p[i] = 0.f;
}
__global__ void k_reset_bar(unsigned* b) {
    if (threadIdx.x < 4) b[threadIdx.x] = 0u;
}
__global__ void k_permbias(const float* __restrict__ bias, float* __restrict__ pb) {
    int n = blockIdx.x * blockDim.x + threadIdx.x;
    if (n < G4U) pb[permcol(n)] = bias[n];
}

__global__ void k_build_enc(const int* __restrict__ X, const float* __restrict__ emb,
                            const float* __restrict__ C, __nv_bfloat16* __restrict__ out) {
    int bt = blockIdx.x;
    int b = bt / NT;
    __nv_bfloat16* row = out + (size_t)bt * UU;
    int x = X[bt];
    for (int i = threadIdx.x; i < UU; i += blockDim.x) {
        float v = 0.f;
        if (i < LATD) v = emb[x * LATD + i];
        else if (i < LATD + PP) v = C[b * PP + (i - LATD)];
        row[i] = __float2bfloat16_rn(v);
    }
}
__global__ void k_build_dec(const int* __restrict__ X, const float* __restrict__ emb,
                            const float* __restrict__ C, const float* __restrict__ zl,
                            __nv_bfloat16* __restrict__ out) {
    int bt = blockIdx.x;
    int b = bt / NT;
    __nv_bfloat16* row = out + (size_t)bt * UU;
    int x = X[bt];
    for (int i = threadIdx.x; i < UU; i += blockDim.x) {
        float v = 0.f;
        if (i < LATD) v = zl[b * LATD + i];
        else if (i < 2 * LATD) v = emb[x * LATD + (i - LATD)];
        else if (i < 2 * LATD + PP) v = C[b * PP + (i - 2 * LATD)];
        row[i] = __float2bfloat16_rn(v);
    }
}

__global__ void k_convT(const float* __restrict__ W, int K, __nv_bfloat16* __restrict__ Wt) {
    __shared__ float tile[32][33];
    int nb0 = blockIdx.x * 32;
    int kb0 = blockIdx.y * 32;
    for (int i = threadIdx.x; i < 1024; i += blockDim.x) {
        int r = i >> 5, c = i & 31;
        tile[r][c] = (kb0 + r < K) ? W[(size_t)(kb0 + r) * G4U + nb0 + c] : 0.f;
    }
    __syncthreads();
    for (int i = threadIdx.x; i < 1024; i += blockDim.x) {
        int r = i >> 5, c = i & 31;
        Wt[(size_t)permcol(nb0 + r) * UU + kb0 + c] = __float2bfloat16_rn(tile[c][r]);
    }
}

__global__ void k_convT_tf32(const float* __restrict__ W, unsigned* __restrict__ Wt) {
    __shared__ float tile[32][33];
    int nb0 = blockIdx.x * 32;
    int kb0 = blockIdx.y * 32;
    for (int i = threadIdx.x; i < 1024; i += blockDim.x) {
        int r = i >> 5, c = i & 31;
        tile[r][c] = W[(size_t)(kb0 + r) * G4U + nb0 + c];
    }
    __syncthreads();
    for (int i = threadIdx.x; i < 1024; i += blockDim.x) {
        int r = i >> 5, c = i & 31;
        Wt[(size_t)(nb0 + r) * UU + kb0 + c] = f2tf32(tile[c][r]);
    }
}

// ---------------- big GEMM, cp.async double-buffered ----------------
#define GS (128 * 72)
#define SMEM_GEMM (4 * GS * 2)

__global__ __launch_bounds__(256) void k_gemm_bf16(
    const __nv_bfloat16* __restrict__ A, const __nv_bfloat16* __restrict__ Wt,
    const float* __restrict__ bias, float* __restrict__ Co) {
    extern __shared__ __nv_bfloat16 gsm[];
    int tid = threadIdx.x;
    int wid = tid >> 5, lane = tid & 31;
    int wm = wid >> 1, wn = wid & 1;
    int lq = lane >> 2, lr = lane & 3;
    int row0 = blockIdx.y * 128, col0 = blockIdx.x * 128;

    float c[2][8][4];
#pragma unroll
    for (int mt = 0; mt < 2; mt++)
#pragma unroll
        for (int nt = 0; nt < 8; nt++)
#pragma unroll
            for (int j = 0; j < 4; j++) c[mt][nt][j] = 0.f;

    auto load_chunk = [&](int buf, int kk) {
        __nv_bfloat16* As_ = gsm + buf * 2 * GS;
        __nv_bfloat16* Bs_ = As_ + GS;
#pragma unroll
        for (int j = 0; j < 4; j++) {
            int i = tid + j * 256;
            int r = i >> 3, c8 = (i & 7) * 8;
            cp16(&As_[r * 72 + c8], &A[(size_t)(row0 + r) * UU + kk + c8]);
            cp16(&Bs_[r * 72 + c8], &Wt[(size_t)(col0 + r) * UU + kk + c8]);
        }
    };

    load_chunk(0, 0);
    CP_COMMIT();

    for (int kc = 0; kc < 8; kc++) {
        if (kc < 7) {
            load_chunk((kc + 1) & 1, (kc + 1) * 64);
            CP_COMMIT();
            CP_WAIT(1);
        } else {
            CP_WAIT(0);
        }
        __syncthreads();
        const __nv_bfloat16* As_ = gsm + (kc & 1) * 2 * GS;
        const __nv_bfloat16* Bs_ = As_ + GS;
#pragma unroll
        for (int ks = 0; ks < 4; ks++) {
            int kb = ks * 16;
            unsigned af[2][4];
#pragma unroll
            for (int mt = 0; mt < 2; mt++) {
                int mb = wm * 32 + mt * 16;
                af[mt][0] = *(const unsigned*)&As_[(mb + lq) * 72 + kb + 2 * lr];
                af[mt][1] = *(const unsigned*)&As_[(mb + lq + 8) * 72 + kb + 2 * lr];
                af[mt][2] = *(const unsigned*)&As_[(mb + lq) * 72 + kb + 8 + 2 * lr];
                af[mt][3] = *(const unsigned*)&As_[(mb + lq + 8) * 72 + kb + 8 + 2 * lr];
            }
#pragma unroll
            for (int nt = 0; nt < 8; nt++) {
                int nb = wn * 64 + nt * 8;
                unsigned bf[2];
                bf[0] = *(const unsigned*)&Bs_[(nb + lq) * 72 + kb + 2 * lr];
                bf[1] = *(const unsigned*)&Bs_[(nb + lq) * 72 + kb + 8 + 2 * lr];
#pragma unroll
                for (int mt = 0; mt < 2; mt++) mma_bf16(c[mt][nt], af[mt], bf);
            }
        }
        __syncthreads();
    }
#pragma unroll
    for (int mt = 0; mt < 2; mt++) {
        size_t rb = (size_t)(row0 + wm * 32 + mt * 16 + lq);
#pragma unroll
        for (int nt = 0; nt < 8; nt++) {
            int cb = col0 + wn * 64 + nt * 8 + 2 * lr;
            float b0 = bias[cb], b1 = bias[cb + 1];
            Co[rb * G4U + cb]           = c[mt][nt][0] + b0;
            Co[rb * G4U + cb + 1]       = c[mt][nt][1] + b1;
            Co[(rb + 8) * G4U + cb]     = c[mt][nt][2] + b0;
            Co[(rb + 8) * G4U + cb + 1] = c[mt][nt][3] + b1;
        }
    }
}

// ---------------- persistent tf32 scan: 512 threads, 2 k-teams ----------------
#define SC_WS 516
#define SC_HS 132
#define SMEM_SCAN (64*SC_WS*4 + 2*64*SC_HS*4 + 64*68*4 + 64*16*4)

__global__ __launch_bounds__(512) void k_scan_tf32(
    const float* __restrict__ Z, const unsigned* __restrict__ rkt,
    float* __restrict__ h0buf, float* __restrict__ h1buf,
    __nv_bfloat16* __restrict__ hseq, float* __restrict__ hseq32,
    float* __restrict__ cfin, volatile unsigned* bar, int mode) {
    extern __shared__ char smraw[];
    unsigned* Wsm = (unsigned*)smraw;
    float* hsm0 = (float*)(smraw + 64 * SC_WS * 4);
    float* hsm1 = hsm0 + 64 * SC_HS;
    float* zsm = (float*)(smraw + 64 * SC_WS * 4 + 2 * 64 * SC_HS * 4);
    float* csm = zsm + 64 * 68;

    int tid = threadIdx.x;
    int wid = tid >> 5, lane = tid & 31;
    int kt = wid & 1;                 // k-team: ks 0..7 vs 8..15
    int wn = (wid >> 1) & 1;          // 2 n-slices of 32 gate-cols
    int wm = (wid >> 2) & 3;          // 4 m-slices of 16 rows
    int lq = lane >> 2, lr = lane & 3;
    int u0 = blockIdx.x * 16;
    int b0 = blockIdx.y * 64;
    volatile unsigned* mybar = bar + blockIdx.y;

    // load rk slice once
    for (int i = tid; i < 64 * 128; i += 512) {
        int nl = i >> 7, kq = (i & 127) * 4;
        int n = (nl >> 4) * 512 + u0 + (nl & 15);
        *(uint4*)&Wsm[nl * SC_WS + kq] = *(const uint4*)&rkt[(size_t)n * UU + kq];
    }
    for (int i = tid; i < 1024; i += 512) csm[i] = 0.f;
    for (int i = tid; i < 64 * 68; i += 512) zsm[i] = 0.f;
    __syncthreads();

    for (int t = 0; t < NT; t++) {
        float4 zreg[2];
#pragma unroll
        for (int rep = 0; rep < 2; rep++) {
            int e = rep * 512 + tid;
            int bl = e >> 4, ulx = e & 15;
            zreg[rep] = __ldg((const float4*)&Z[(((size_t)(b0 + bl) * NT + t) << 11) +
                                                ((u0 + ulx) << 2)]);
        }

        float acc[4][4];
#pragma unroll
        for (int nt = 0; nt < 4; nt++)
#pragma unroll
            for (int j = 0; j < 4; j++) acc[nt][j] = 0.f;

        if (t > 0) {
            if (tid == 0) {
                unsigned target = (unsigned)t * DOM_BLOCKS;
                while (*mybar < target) {}
            }
            __syncthreads();
            const float* hprev = ((t - 1) & 1) ? h1buf : h0buf;

#pragma unroll
            for (int j = 0; j < 4; j++) {
                int i = tid + j * 512;
                int r = i >> 5, cq = (i & 31) * 4;
                cp16(&hsm0[r * SC_HS + cq], &hprev[(size_t)(b0 + r) * UU + cq]);
            }
            CP_COMMIT();

            int mb = wm * 16;
            for (int kc = 0; kc < 4; kc++) {
                float* cur = (kc & 1) ? hsm1 : hsm0;
                float* nxt = (kc & 1) ? hsm0 : hsm1;
                if (kc < 3) {
                    int kk = (kc + 1) * 128;
#pragma unroll
                    for (int j = 0; j < 4; j++) {
                        int i = tid + j * 512;
                        int r = i >> 5, cq = (i & 31) * 4;
                        cp16(&nxt[r * SC_HS + cq], &hprev[(size_t)(b0 + r) * UU + kk + cq]);
                    }
                    CP_COMMIT();
                    CP_WAIT(1);
                } else {
                    CP_WAIT(0);
                }
                __syncthreads();
                const unsigned* cu = (const unsigned*)cur;
#pragma unroll
                for (int ks = 0; ks < 8; ks++) {
                    int kb = (kt * 8 + ks) * 8;
                    unsigned af[4];
                    af[0] = cu[(mb + lq) * SC_HS + kb + lr];
                    af[1] = cu[(mb + lq + 8) * SC_HS + kb + lr];
                    af[2] = cu[(mb + lq) * SC_HS + kb + lr + 4];
                    af[3] = cu[(mb + lq + 8) * SC_HS + kb + lr + 4];
#pragma unroll
                    for (int nt = 0; nt < 4; nt++) {
                        int nb = wn * 32 + nt * 8;
                        unsigned bf[2];
                        bf[0] = Wsm[(nb + lq) * SC_WS + kc * 128 + kb + lr];
                        bf[1] = Wsm[(nb + lq) * SC_WS + kc * 128 + kb + lr + 4];
                        mma_tf32(acc[nt], af, bf);
                    }
                }
                __syncthreads();
            }

            // merge both k-teams into zsm via smem atomics
            int rb = wm * 16 + lq;
#pragma unroll
            for (int nt = 0; nt < 4; nt++) {
                int cb = wn * 32 + nt * 8 + 2 * lr;
                atomicAdd(&zsm[rb * 68 + cb],           acc[nt][0]);
                atomicAdd(&zsm[rb * 68 + cb + 1],       acc[nt][1]);
                atomicAdd(&zsm[(rb + 8) * 68 + cb],     acc[nt][2]);
                atomicAdd(&zsm[(rb + 8) * 68 + cb + 1], acc[nt][3]);
            }
        }
        __syncthreads();

        // LSTM update: 64b x 16u, 2 outputs/thread; zero zsm in-place after read
        float* hnext = (t & 1) ? h1buf : h0buf;
#pragma unroll
        for (int rep = 0; rep < 2; rep++) {
            int e = rep * 512 + tid;
            int bl = e >> 4, ulx = e & 15;
            int b = b0 + bl, u = u0 + ulx;
            float zi = zsm[bl * 68 + ulx]      + zreg[rep].x;
            float zf = zsm[bl * 68 + 16 + ulx] + zreg[rep].y;
            float zg = zsm[bl * 68 + 32 + ulx] + zreg[rep].z;
            float zo = zsm[bl * 68 + 48 + ulx] + zreg[rep].w;
            zsm[bl * 68 + ulx] = 0.f;
            zsm[bl * 68 + 16 + ulx] = 0.f;
            zsm[bl * 68 + 32 + ulx] = 0.f;
            zsm[bl * 68 + 48 + ulx] = 0.f;
            float co = csm[bl * 16 + ulx];
            float c2 = sigm(zf) * co + sigm(zi) * tanhf(zg);
            float h2 = sigm(zo) * tanhf(c2);
            csm[bl * 16 + ulx] = c2;
            __stcg(&hnext[(size_t)b * UU + u], __uint_as_float(f2tf32(h2)));
            size_t so = ((size_t)b * NT + t) * UU + u;
            if (mode & 1) hseq[so] = __float2bfloat16_rn(h2);
            if (mode & 2) hseq32[so] = h2;
        }

        if (t < NT - 1) {
            __threadfence();
            __syncthreads();
            if (tid == 0) atomicAdd((unsigned*)mybar, 1u);
        }
    }
#pragma unroll
    for (int rep = 0; rep < 2; rep++) {
        int e = rep * 512 + tid;
        int bl = e >> 4, ulx = e & 15;
        cfin[(b0 + bl) * UU + u0 + ulx] = csm[bl * 16 + ulx];
    }
}

// ---------------- mean / log_sigma / reparameterize ----------------
__global__ void k_mean_ls(const float* __restrict__ cst,
                          const float* __restrict__ Wm, const float* __restrict__ bm,
                          const float* __restrict__ Ws, const float* __restrict__ bs,
                          const float* __restrict__ eps,
                          float* __restrict__ mo, float* __restrict__ lo, float* __restrict__ zo) {
    int idx = blockIdx.x * blockDim.x + threadIdx.x;
    if (idx >= NB * LATD) return;
    int b = idx / LATD, l = idx % LATD;
    const float* cr = cst + b * UU;
    float m = bm[l], s = bs[l];
    for (int k = 0; k < UU; k++) {
        float cv = cr[k];
        m += cv * Wm[k * LATD + l];
        s += cv * Ws[k * LATD + l];
    }
    mo[idx] = m;
    lo[idx] = s;
    zo[idx] = m + expf(0.5f * s) * eps[idx];
}

__global__ void k_latent(const float* __restrict__ mo, const float* __restrict__ lo,
                         float* __restrict__ acc) {
    __shared__ float sdata[256];
    int idx = blockIdx.x * blockDim.x + threadIdx.x;
    float v = 0.f;
    if (idx < NB * LATD) {
        float m = mo[idx], s = lo[idx];
        v = 1.f + s - m * m - expf(s);
    }
    sdata[threadIdx.x] = v;
    __syncthreads();
    for (int o = 128; o > 0; o >>= 1) {
        if (threadIdx.x < o) sdata[threadIdx.x] += sdata[threadIdx.x + o];
        __syncthreads();
    }
    if (threadIdx.x == 0) atomicAdd(acc + 1, sdata[0]);
}

// ---------------- fused logits + log-softmax + masked CE (fp32 h) ----------------
__global__ void k_ce(const float* __restrict__ H, const float* __restrict__ Wo,
                     const float* __restrict__ bo, const int* __restrict__ Y,
                     const int* __restrict__ L, float* __restrict__ acc) {
    __shared__ float hs[8][UU];
    int row0 = blockIdx.x * 8;
    for (int i = threadIdx.x; i < 8 * UU; i += 256) {
        int r = i >> 9, k = i & 511;
        hs[r][k] = H[(size_t)(row0 + r) * UU + k];
    }
    __syncthreads();
    int w = threadIdx.x >> 5, lane = threadIdx.x & 31;
    int row = row0 + w;
    int b = row / NT, t = row % NT;

    float d0 = 0.f, d1 = 0.f;
    bool has1 = (lane + 32) < VOC;
    for (int k = 0; k < UU; k++) {
        float hv = hs[w][k];
        d0 += hv * Wo[k * VOC + lane];
        if (has1) d1 += hv * Wo[k * VOC + lane + 32];
    }
    float p0 = d0 + bo[lane];
    float p1 = has1 ? (d1 + bo[lane + 32]) : -1e30f;
    float m = fmaxf(p0, p1);
#pragma unroll
    for (int o = 16; o; o >>= 1) m = fmaxf(m, __shfl_xor_sync(0xffffffffu, m, o));
    float e = expf(p0 - m) + (has1 ? expf(p1 - m) : 0.f);
#pragma unroll
    for (int o = 16; o; o >>= 1) e += __shfl_xor_sync(0xffffffffu, e, o);
    float lse = logf(e) + m;
    int y = Y[row];
    float py = __shfl_sync(0xffffffffu, (y < 32) ? p0 : p1, y & 31);
    if (lane == 0) {
        float wt = (t < L[b]) ? 1.f : 0.f;
        atomicAdd(acc, (lse - py) * wt);
    }
}

__global__ void k_final(const float* __restrict__ acc, float* __restrict__ out, int out_size) {
    if (threadIdx.x == 0) {
        float recon = acc[0] / (float)BT;
        float lat = -0.5f * acc[1] / (float)(NB * LATD);
        if (out_size > 0) out[0] = recon + lat;
        if (out_size > 1) out[1] = recon;
        if (out_size > 2) out[2] = lat;
    }
}

// ---------------- host driver ----------------
extern "C" void kernel_launch(void* const* d_in, const int* in_sizes, int n_in,
                              void* d_out, int out_size) {
    const int*   X       = (const int*)d_in[0];
    const int*   Y       = (const int*)d_in[1];
    const float* C       = (const float*)d_in[2];
    const int*   L       = (const int*)d_in[3];
    const float* eps     = (const float*)d_in[4];
    const float* emb_enc = (const float*)d_in[5];
    const float* emb_dec = (const float*)d_in[6];
    const float* enc_k[3]  = {(const float*)d_in[7],  (const float*)d_in[10], (const float*)d_in[13]};
    const float* enc_rk[3] = {(const float*)d_in[8],  (const float*)d_in[11], (const float*)d_in[14]};
    const float* enc_b[3]  = {(const float*)d_in[9],  (const float*)d_in[12], (const float*)d_in[15]};
    const float* dec_k[3]  = {(const float*)d_in[16], (const float*)d_in[19], (const float*)d_in[22]};
    const float* dec_rk[3] = {(const float*)d_in[17], (const float*)d_in[20], (const float*)d_in[23]};
    const float* dec_b[3]  = {(const float*)d_in[18], (const float*)d_in[21], (const float*)d_in[24]};
    const float* Wm = (const float*)d_in[25];
    const float* bm = (const float*)d_in[26];
    const float* Ws = (const float*)d_in[27];
    const float* bs = (const float*)d_in[28];
    const float* Wo = (const float*)d_in[29];
    const float* bo = (const float*)d_in[30];

    __nv_bfloat16 *bufA, *bufB, *wt;
    unsigned *rkt, *bar;
    float *Zb, *cst, *mo, *lo, *zl, *acc, *h0, *h1, *hf32, *pb;
    cudaGetSymbolAddress((void**)&bufA, g_bufA);
    cudaGetSymbolAddress((void**)&bufB, g_bufB);
    cudaGetSymbolAddress((void**)&wt,   g_wt);
    cudaGetSymbolAddress((void**)&rkt,  g_rkt);
    cudaGetSymbolAddress((void**)&Zb,   g_Z);
    cudaGetSymbolAddress((void**)&cst,  g_c);
    cudaGetSymbolAddress((void**)&mo,   g_mean);
    cudaGetSymbolAddress((void**)&lo,   g_ls);
    cudaGetSymbolAddress((void**)&zl,   g_zlat);
    cudaGetSymbolAddress((void**)&acc,  g_acc);
    cudaGetSymbolAddress((void**)&h0,   g_h0);
    cudaGetSymbolAddress((void**)&h1,   g_h1);
    cudaGetSymbolAddress((void**)&hf32, g_hf32);
    cudaGetSymbolAddress((void**)&pb,   g_pbias);
    cudaGetSymbolAddress((void**)&bar,  g_bar);

    static int smem_set = 0;
    if (!smem_set) {
        cudaFuncSetAttribute(k_scan_tf32, cudaFuncAttributeMaxDynamicSharedMemorySize, SMEM_SCAN);
        cudaFuncSetAttribute(k_gemm_bf16, cudaFuncAttributeMaxDynamicSharedMemorySize, SMEM_GEMM);
        smem_set = 1;
    }

    k_zero<<<1, 64>>>(acc, 2);

    dim3 gemm_grid(G4U / 128, BT / 128);
    dim3 conv_grid(64, 16);
    dim3 scan_grid(32, 4);

    const int encKs[3] = {LATD + PP, UU, UU};
    const int decKs[3] = {2 * LATD + PP, UU, UU};
    const int encMode[3] = {1, 1, 0};   // enc l2: only cfin needed
    const int decMode[3] = {1, 1, 2};   // dec l2: fp32 hseq for CE

    // ======== encoder ========
    k_build_enc<<<BT, 256>>>(X, emb_enc, C, bufA);
    {
        __nv_bfloat16* inb = bufA;
        __nv_bfloat16* outb = bufB;
        for (int l = 0; l < 3; l++) {
            k_convT<<<conv_grid, 256>>>(enc_k[l], encKs[l], wt);
            k_permbias<<<8, 256>>>(enc_b[l], pb);
            k_gemm_bf16<<<gemm_grid, 256, SMEM_GEMM>>>(inb, wt, pb, Zb);
            k_convT_tf32<<<conv_grid, 256>>>(enc_rk[l], rkt);
            k_reset_bar<<<1, 32>>>(bar);
            k_scan_tf32<<<scan_grid, 512, SMEM_SCAN>>>(Zb, rkt, h0, h1, outb, hf32, cst, bar, encMode[l]);
            __nv_bfloat16* tmp = inb; inb = outb; outb = tmp;
        }
    }
    k_mean_ls<<<(NB * LATD + 255) / 256, 256>>>(cst, Wm, bm, Ws, bs, eps, mo, lo, zl);
    k_latent<<<(NB * LATD + 255) / 256, 256>>>(mo, lo, acc);

    // ======== decoder ========
    k_build_dec<<<BT, 256>>>(X, emb_dec, C, zl, bufA);
    {
        __nv_bfloat16* inb = bufA;
        __nv_bfloat16* outb = bufB;
        for (int l = 0; l < 3; l++) {
            k_convT<<<conv_grid, 256>>>(dec_k[l], decKs[l], wt);
            k_permbias<<<8, 256>>>(dec_b[l], pb);
            k_gemm_bf16<<<gemm_grid, 256, SMEM_GEMM>>>(inb, wt, pb, Zb);
            k_convT_tf32<<<conv_grid, 256>>>(dec_rk[l], rkt);
            k_reset_bar<<<1, 32>>>(bar);
            k_scan_tf32<<<scan_grid, 512, SMEM_SCAN>>>(Zb, rkt, h0, h1, outb, hf32, cst, bar, decMode[l]);
            __nv_bfloat16* tmp = inb; inb = outb; outb = tmp;
        }
    }

    // ======== losses ========
    k_ce<<<BT / 8, 256>>>(hf32, Wo, bo, Y, L, acc);
    k_final<<<1, 32>>>(acc, (float*)d_out, out_size);
}

// round 10
// speedup vs baseline: 1.2538x; 1.0680x over previous
#include <cuda_runtime.h>
#include <cuda_bf16.h>
#include <math.h>

#define NB   256
#define NT   128
#define VOC  42
#define LATD 200
#define UU   512
#define PP   3
#define BT   (NB*NT)
#define G4U  2048
#define DOM_BLOCKS 32

// ---------------- device scratch ----------------
__device__ __nv_bfloat16 g_bufA[(size_t)BT*UU];
__device__ __nv_bfloat16 g_bufB[(size_t)BT*UU];
__device__ float g_Z[(size_t)BT*G4U];              // gate-interleaved: [b,t,u,4]
__device__ float g_hf32[(size_t)BT*UU];            // fp32 hseq (for CE)
__device__ __nv_bfloat16 g_wt[(size_t)G4U*UU];     // permuted weight^T bf16
__device__ float g_pbias[G4U];                     // permuted bias
__device__ unsigned g_rkt[(size_t)G4U*UU];         // recurrent W^T tf32, k-permuted
__device__ float g_h0[NB*UU];                      // h ping (k-permuted u layout)
__device__ float g_h1[NB*UU];                      // h pong (k-permuted u layout)
__device__ float g_c[NB*UU];
__device__ float g_mean[NB*LATD];
__device__ float g_ls[NB*LATD];
__device__ float g_zlat[NB*LATD];
__device__ float g_acc[2];
__device__ unsigned g_bar[4];

__device__ __forceinline__ int permcol(int n) { return ((n & 511) << 2) | (n >> 9); }
// k-permutation within 8-groups: logical (lr, lr+4) -> phys (2lr, 2lr+1)
__device__ __forceinline__ int kperm(int k) {
    return (k & ~7) | ((k & 3) << 1) | ((k >> 2) & 1);
}

// ---------------- helpers ----------------
__device__ __forceinline__ unsigned f2tf32(float x) {
    unsigned r;
    asm("cvt.rna.tf32.f32 %0, %1;" : "=r"(r) : "f"(x));
    return r;
}
__device__ __forceinline__ void mma_tf32(float c[4], const unsigned a[4], const unsigned b[2]) {
    asm volatile(
        "mma.sync.aligned.m16n8k8.row.col.f32.tf32.tf32.f32 "
        "{%0,%1,%2,%3}, {%4,%5,%6,%7}, {%8,%9}, {%0,%1,%2,%3};\n"
        : "+f"(c[0]), "+f"(c[1]), "+f"(c[2]), "+f"(c[3])
        : "r"(a[0]), "r"(a[1]), "r"(a[2]), "r"(a[3]), "r"(b[0]), "r"(b[1]));
}
__device__ __forceinline__ void mma_bf16(float c[4], const unsigned a[4], const unsigned b[2]) {
    asm volatile(
        "mma.sync.aligned.m16n8k16.row.col.f32.bf16.bf16.f32 "
        "{%0,%1,%2,%3}, {%4,%5,%6,%7}, {%8,%9}, {%0,%1,%2,%3};\n"
        : "+f"(c[0]), "+f"(c[1]), "+f"(c[2]), "+f"(c[3])
        : "r"(a[0]), "r"(a[1]), "r"(a[2]), "r"(a[3]), "r"(b[0]), "r"(b[1]));
}
__device__ __forceinline__ float sigm(float x) { return 1.f / (1.f + expf(-x)); }

__device__ __forceinline__ void cp16(void* s, const void* g) {
    unsigned sa = (unsigned)__cvta_generic_to_shared(s);
    asm volatile("cp.async.cg.shared.global [%0], [%1], 16;\n" :: "r"(sa), "l"(g));
}
#define CP_COMMIT() asm volatile("cp.async.commit_group;\n")
#define CP_WAIT(n)  asm volatile("cp.async.wait_group %0;\n" :: "n"(n))

// ---------------- utility kernels ----------------
__global__ void k_zero(float* p, int n) {
    int i = blockIdx.x * blockDim.x + threadIdx.x;
    if (i < n) p[i] = 0.f;
}
__global__ void k_reset_bar(unsigned* b) {
    if (threadIdx.x < 4) b[threadIdx.x] = 0u;
}
__global__ void k_permbias(const float* __restrict__ bias, float* __restrict__ pb) {
    int n = blockIdx.x * blockDim.x + threadIdx.x;
    if (n < G4U) pb[permcol(n)] = bias[n];
}

__global__ void k_build_enc(const int* __restrict__ X, const float* __restrict__ emb,
                            const float* __restrict__ C, __nv_bfloat16* __restrict__ out) {
    int bt = blockIdx.x;
    int b = bt / NT;
    __nv_bfloat16* row = out + (size_t)bt * UU;
    int x = X[bt];
    for (int i = threadIdx.x; i < UU; i += blockDim.x) {
        float v = 0.f;
        if (i < LATD) v = emb[x * LATD + i];
        else if (i < LATD + PP) v = C[b * PP + (i - LATD)];
        row[i] = __float2bfloat16_rn(v);
    }
}
__global__ void k_build_dec(const int* __restrict__ X, const float* __restrict__ emb,
                            const float* __restrict__ C, const float* __restrict__ zl,
                            __nv_bfloat16* __restrict__ out) {
    int bt = blockIdx.x;
    int b = bt / NT;
    __nv_bfloat16* row = out + (size_t)bt * UU;
    int x = X[bt];
    for (int i = threadIdx.x; i < UU; i += blockDim.x) {
        float v = 0.f;
        if (i < LATD) v = zl[b * LATD + i];
        else if (i < 2 * LATD) v = emb[x * LATD + (i - LATD)];
        else if (i < 2 * LATD + PP) v = C[b * PP + (i - 2 * LATD)];
        row[i] = __float2bfloat16_rn(v);
    }
}

__global__ void k_convT(const float* __restrict__ W, int K, __nv_bfloat16* __restrict__ Wt) {
    __shared__ float tile[32][33];
    int nb0 = blockIdx.x * 32;
    int kb0 = blockIdx.y * 32;
    for (int i = threadIdx.x; i < 1024; i += blockDim.x) {
        int r = i >> 5, c = i & 31;
        tile[r][c] = (kb0 + r < K) ? W[(size_t)(kb0 + r) * G4U + nb0 + c] : 0.f;
    }
    __syncthreads();
    for (int i = threadIdx.x; i < 1024; i += blockDim.x) {
        int r = i >> 5, c = i & 31;
        Wt[(size_t)permcol(nb0 + r) * UU + kb0 + c] = __float2bfloat16_rn(tile[c][r]);
    }
}

// rk fp32 [512][2048] -> rkt tf32 [2048][kperm(512)]
__global__ void k_convT_tf32(const float* __restrict__ W, unsigned* __restrict__ Wt) {
    __shared__ float tile[32][33];
    int nb0 = blockIdx.x * 32;
    int kb0 = blockIdx.y * 32;
    for (int i = threadIdx.x; i < 1024; i += blockDim.x) {
        int r = i >> 5, c = i & 31;
        tile[r][c] = W[(size_t)(kb0 + r) * G4U + nb0 + c];
    }
    __syncthreads();
    for (int i = threadIdx.x; i < 1024; i += blockDim.x) {
        int r = i >> 5, c = i & 31;
        Wt[(size_t)(nb0 + r) * UU + kb0 + kperm(c)] = f2tf32(tile[c][r]);
    }
}

// ---------------- big GEMM, cp.async double-buffered ----------------
#define GS (128 * 72)
#define SMEM_GEMM (4 * GS * 2)

__global__ __launch_bounds__(256) void k_gemm_bf16(
    const __nv_bfloat16* __restrict__ A, const __nv_bfloat16* __restrict__ Wt,
    const float* __restrict__ bias, float* __restrict__ Co) {
    extern __shared__ __nv_bfloat16 gsm[];
    int tid = threadIdx.x;
    int wid = tid >> 5, lane = tid & 31;
    int wm = wid >> 1, wn = wid & 1;
    int lq = lane >> 2, lr = lane & 3;
    int row0 = blockIdx.y * 128, col0 = blockIdx.x * 128;

    float c[2][8][4];
#pragma unroll
    for (int mt = 0; mt < 2; mt++)
#pragma unroll
        for (int nt = 0; nt < 8; nt++)
#pragma unroll
            for (int j = 0; j < 4; j++) c[mt][nt][j] = 0.f;

    auto load_chunk = [&](int buf, int kk) {
        __nv_bfloat16* As_ = gsm + buf * 2 * GS;
        __nv_bfloat16* Bs_ = As_ + GS;
#pragma unroll
        for (int j = 0; j < 4; j++) {
            int i = tid + j * 256;
            int r = i >> 3, c8 = (i & 7) * 8;
            cp16(&As_[r * 72 + c8], &A[(size_t)(row0 + r) * UU + kk + c8]);
            cp16(&Bs_[r * 72 + c8], &Wt[(size_t)(col0 + r) * UU + kk + c8]);
        }
    };

    load_chunk(0, 0);
    CP_COMMIT();

    for (int kc = 0; kc < 8; kc++) {
        if (kc < 7) {
            load_chunk((kc + 1) & 1, (kc + 1) * 64);
            CP_COMMIT();
            CP_WAIT(1);
        } else {
            CP_WAIT(0);
        }
        __syncthreads();
        const __nv_bfloat16* As_ = gsm + (kc & 1) * 2 * GS;
        const __nv_bfloat16* Bs_ = As_ + GS;
#pragma unroll
        for (int ks = 0; ks < 4; ks++) {
            int kb = ks * 16;
            unsigned af[2][4];
#pragma unroll
            for (int mt = 0; mt < 2; mt++) {
                int mb = wm * 32 + mt * 16;
                af[mt][0] = *(const unsigned*)&As_[(mb + lq) * 72 + kb + 2 * lr];
                af[mt][1] = *(const unsigned*)&As_[(mb + lq + 8) * 72 + kb + 2 * lr];
                af[mt][2] = *(const unsigned*)&As_[(mb + lq) * 72 + kb + 8 + 2 * lr];
                af[mt][3] = *(const unsigned*)&As_[(mb + lq + 8) * 72 + kb + 8 + 2 * lr];
            }
#pragma unroll
            for (int nt = 0; nt < 8; nt++) {
                int nb = wn * 64 + nt * 8;
                unsigned bf[2];
                bf[0] = *(const unsigned*)&Bs_[(nb + lq) * 72 + kb + 2 * lr];
                bf[1] = *(const unsigned*)&Bs_[(nb + lq) * 72 + kb + 8 + 2 * lr];
#pragma unroll
                for (int mt = 0; mt < 2; mt++) mma_bf16(c[mt][nt], af[mt], bf);
            }
        }
        __syncthreads();
    }
#pragma unroll
    for (int mt = 0; mt < 2; mt++) {
        size_t rb = (size_t)(row0 + wm * 32 + mt * 16 + lq);
#pragma unroll
        for (int nt = 0; nt < 8; nt++) {
            int cb = col0 + wn * 64 + nt * 8 + 2 * lr;
            float b0 = bias[cb], b1 = bias[cb + 1];
            Co[rb * G4U + cb]           = c[mt][nt][0] + b0;
            Co[rb * G4U + cb + 1]       = c[mt][nt][1] + b1;
            Co[(rb + 8) * G4U + cb]     = c[mt][nt][2] + b0;
            Co[(rb + 8) * G4U + cb + 1] = c[mt][nt][3] + b1;
        }
    }
}

// ---------------- persistent tf32 scan: operand-swapped, LDS.64 fragments ----------------
// A = rk slice (Wsm, m=64 gate-cols), B = h (hsm, n=64 batches), both k-permuted.
// 512 threads = 16 warps: kt(2 k-teams) x wm(2 gate-halves of 32) x wn(4 batch-quarters of 16).
#define SC_WS 520
#define SC_HS 136
#define SMEM_SCAN (64*SC_WS*4 + 2*64*SC_HS*4 + 64*68*4 + 64*16*4)

__global__ __launch_bounds__(512) void k_scan_tf32(
    const float* __restrict__ Z, const unsigned* __restrict__ rkt,
    float* __restrict__ h0buf, float* __restrict__ h1buf,
    __nv_bfloat16* __restrict__ hseq, float* __restrict__ hseq32,
    float* __restrict__ cfin, volatile unsigned* bar, int mode) {
    extern __shared__ char smraw[];
    unsigned* Wsm = (unsigned*)smraw;                                   // [64][520]
    float* hsm0 = (float*)(smraw + 64 * SC_WS * 4);                     // [64][136]
    float* hsm1 = hsm0 + 64 * SC_HS;
    float* zsm = (float*)(smraw + 64 * SC_WS * 4 + 2 * 64 * SC_HS * 4); // [64][68]
    float* csm = zsm + 64 * 68;                                          // [64][16]

    int tid = threadIdx.x;
    int wid = tid >> 5, lane = tid & 31;
    int kt = wid & 1;                 // k-team
    int wm = (wid >> 1) & 1;          // gate-half (32 gate-cols)
    int wn = wid >> 2;                // batch-quarter (16 batches), 0..3
    int lq = lane >> 2, lr = lane & 3;
    int u0 = blockIdx.x * 16;
    int b0 = blockIdx.y * 64;
    volatile unsigned* mybar = bar + blockIdx.y;

    // load rk slice once (rows = gatecol g = gate*16+ulocal; k already permuted)
    for (int i = tid; i < 64 * 128; i += 512) {
        int nl = i >> 7, kq = (i & 127) * 4;
        int n = (nl >> 4) * 512 + u0 + (nl & 15);
        *(uint4*)&Wsm[nl * SC_WS + kq] = *(const uint4*)&rkt[(size_t)n * UU + kq];
    }
    for (int i = tid; i < 1024; i += 512) csm[i] = 0.f;
    for (int i = tid; i < 64 * 68; i += 512) zsm[i] = 0.f;
    __syncthreads();

    for (int t = 0; t < NT; t++) {
        float4 zreg[2];
#pragma unroll
        for (int rep = 0; rep < 2; rep++) {
            int e = rep * 512 + tid;
            int bl = e >> 4, ulx = e & 15;
            zreg[rep] = __ldg((const float4*)&Z[(((size_t)(b0 + bl) * NT + t) << 11) +
                                                ((u0 + ulx) << 2)]);
        }

        float acc[2][2][4];   // [mt][nt][4]
#pragma unroll
        for (int mt = 0; mt < 2; mt++)
#pragma unroll
            for (int nt = 0; nt < 2; nt++)
#pragma unroll
                for (int j = 0; j < 4; j++) acc[mt][nt][j] = 0.f;

        if (t > 0) {
            if (tid == 0) {
                unsigned target = (unsigned)t * DOM_BLOCKS;
                while (*mybar < target) {}
            }
            __syncthreads();
            const float* hprev = ((t - 1) & 1) ? h1buf : h0buf;

#pragma unroll
            for (int j = 0; j < 4; j++) {
                int i = tid + j * 512;
                int r = i >> 5, cq = (i & 31) * 4;
                cp16(&hsm0[r * SC_HS + cq], &hprev[(size_t)(b0 + r) * UU + cq]);
            }
            CP_COMMIT();

            int mb = wm * 32;
            int nbw = wn * 16;
            for (int kc = 0; kc < 4; kc++) {
                float* cur = (kc & 1) ? hsm1 : hsm0;
                float* nxt = (kc & 1) ? hsm0 : hsm1;
                if (kc < 3) {
                    int kk = (kc + 1) * 128;
#pragma unroll
                    for (int j = 0; j < 4; j++) {
                        int i = tid + j * 512;
                        int r = i >> 5, cq = (i & 31) * 4;
                        cp16(&nxt[r * SC_HS + cq], &hprev[(size_t)(b0 + r) * UU + kk + cq]);
                    }
                    CP_COMMIT();
                    CP_WAIT(1);
                } else {
                    CP_WAIT(0);
                }
                __syncthreads();
                const unsigned* cu = (const unsigned*)cur;
#pragma unroll
                for (int ks = 0; ks < 8; ks++) {
                    int kb = kc * 128 + (kt * 8 + ks) * 8 + 2 * lr;
                    unsigned af[2][4];
#pragma unroll
                    for (int mt = 0; mt < 2; mt++) {
                        int row = mb + mt * 16;
                        uint2 p = *(const uint2*)&Wsm[(row + lq) * SC_WS + kb];
                        uint2 q = *(const uint2*)&Wsm[(row + lq + 8) * SC_WS + kb];
                        af[mt][0] = p.x; af[mt][2] = p.y;
                        af[mt][1] = q.x; af[mt][3] = q.y;
                    }
                    int kbh = (kt * 8 + ks) * 8 + 2 * lr;
#pragma unroll
                    for (int nt = 0; nt < 2; nt++) {
                        uint2 r2 = *(const uint2*)&cu[(nbw + nt * 8 + lq) * SC_HS + kbh];
                        unsigned bf[2] = {r2.x, r2.y};
#pragma unroll
                        for (int mt = 0; mt < 2; mt++) mma_tf32(acc[mt][nt], af[mt], bf);
                    }
                }
                __syncthreads();
            }

            // merge k-teams: scatter D(m=gate, n=batch) into zsm[batch][gate]
#pragma unroll
            for (int mt = 0; mt < 2; mt++) {
                int g0 = mb + mt * 16 + lq;
#pragma unroll
                for (int nt = 0; nt < 2; nt++) {
                    int bl = nbw + nt * 8 + 2 * lr;
                    atomicAdd(&zsm[bl * 68 + g0],           acc[mt][nt][0]);
                    atomicAdd(&zsm[(bl + 1) * 68 + g0],     acc[mt][nt][1]);
                    atomicAdd(&zsm[bl * 68 + g0 + 8],       acc[mt][nt][2]);
                    atomicAdd(&zsm[(bl + 1) * 68 + g0 + 8], acc[mt][nt][3]);
                }
            }
        }
        __syncthreads();

        // LSTM update: 64b x 16u, 2 outputs/thread; zero zsm in-place after read
        float* hnext = (t & 1) ? h1buf : h0buf;
#pragma unroll
        for (int rep = 0; rep < 2; rep++) {
            int e = rep * 512 + tid;
            int bl = e >> 4, ulx = e & 15;
            int b = b0 + bl, u = u0 + ulx;
            float zi = zsm[bl * 68 + ulx]      + zreg[rep].x;
            float zf = zsm[bl * 68 + 16 + ulx] + zreg[rep].y;
            float zg = zsm[bl * 68 + 32 + ulx] + zreg[rep].z;
            float zo = zsm[bl * 68 + 48 + ulx] + zreg[rep].w;
            zsm[bl * 68 + ulx] = 0.f;
            zsm[bl * 68 + 16 + ulx] = 0.f;
            zsm[bl * 68 + 32 + ulx] = 0.f;
            zsm[bl * 68 + 48 + ulx] = 0.f;
            float co = csm[bl * 16 + ulx];
            float c2 = sigm(zf) * co + sigm(zi) * tanhf(zg);
            float h2 = sigm(zo) * tanhf(c2);
            csm[bl * 16 + ulx] = c2;
            // store h rounded-to-tf32, at k-permuted u position
            int up = u0 + ((ulx & 8) | ((ulx & 3) << 1) | ((ulx >> 2) & 1));
            __stcg(&hnext[(size_t)b * UU + up], __uint_as_float(f2tf32(h2)));
            size_t so = ((size_t)b * NT + t) * UU + u;
            if (mode & 1) hseq[so] = __float2bfloat16_rn(h2);
            if (mode & 2) hseq32[so] = h2;
        }

        if (t < NT - 1) {
            __threadfence();
            __syncthreads();
            if (tid == 0) atomicAdd((unsigned*)mybar, 1u);
        }
    }
#pragma unroll
    for (int rep = 0; rep < 2; rep++) {
        int e = rep * 512 + tid;
        int bl = e >> 4, ulx = e & 15;
        cfin[(b0 + bl) * UU + u0 + ulx] = csm[bl * 16 + ulx];
    }
}

// ---------------- mean / log_sigma / reparameterize ----------------
__global__ void k_mean_ls(const float* __restrict__ cst,
                          const float* __restrict__ Wm, const float* __restrict__ bm,
                          const float* __restrict__ Ws, const float* __restrict__ bs,
                          const float* __restrict__ eps,
                          float* __restrict__ mo, float* __restrict__ lo, float* __restrict__ zo) {
    int idx = blockIdx.x * blockDim.x + threadIdx.x;
    if (idx >= NB * LATD) return;
    int b = idx / LATD, l = idx % LATD;
    const float* cr = cst + b * UU;
    float m = bm[l], s = bs[l];
    for (int k = 0; k < UU; k++) {
        float cv = cr[k];
        m += cv * Wm[k * LATD + l];
        s += cv * Ws[k * LATD + l];
    }
    mo[idx] = m;
    lo[idx] = s;
    zo[idx] = m + expf(0.5f * s) * eps[idx];
}

__global__ void k_latent(const float* __restrict__ mo, const float* __restrict__ lo,
                         float* __restrict__ acc) {
    __shared__ float sdata[256];
    int idx = blockIdx.x * blockDim.x + threadIdx.x;
    float v = 0.f;
    if (idx < NB * LATD) {
        float m = mo[idx], s = lo[idx];
        v = 1.f + s - m * m - expf(s);
    }
    sdata[threadIdx.x] = v;
    __syncthreads();
    for (int o = 128; o > 0; o >>= 1) {
        if (threadIdx.x < o) sdata[threadIdx.x] += sdata[threadIdx.x + o];
        __syncthreads();
    }
    if (threadIdx.x == 0) atomicAdd(acc + 1, sdata[0]);
}

// ---------------- fused logits + log-softmax + masked CE (fp32 h) ----------------
__global__ void k_ce(const float* __restrict__ H, const float* __restrict__ Wo,
                     const float* __restrict__ bo, const int* __restrict__ Y,
                     const int* __restrict__ L, float* __restrict__ acc) {
    __shared__ float hs[8][UU];
    int row0 = blockIdx.x * 8;
    for (int i = threadIdx.x; i < 8 * UU; i += 256) {
        int r = i >> 9, k = i & 511;
        hs[r][k] = H[(size_t)(row0 + r) * UU + k];
    }
    __syncthreads();
    int w = threadIdx.x >> 5, lane = threadIdx.x & 31;
    int row = row0 + w;
    int b = row / NT, t = row % NT;

    float d0 = 0.f, d1 = 0.f;
    bool has1 = (lane + 32) < VOC;
    for (int k = 0; k < UU; k++) {
        float hv = hs[w][k];
        d0 += hv * Wo[k * VOC + lane];
        if (has1) d1 += hv * Wo[k * VOC + lane + 32];
    }
    float p0 = d0 + bo[lane];
    float p1 = has1 ? (d1 + bo[lane + 32]) : -1e30f;
    float m = fmaxf(p0, p1);
#pragma unroll
    for (int o = 16; o; o >>= 1) m = fmaxf(m, __shfl_xor_sync(0xffffffffu, m, o));
    float e = expf(p0 - m) + (has1 ? expf(p1 - m) : 0.f);
#pragma unroll
    for (int o = 16; o; o >>= 1) e += __shfl_xor_sync(0xffffffffu, e, o);
    float lse = logf(e) + m;
    int y = Y[row];
    float py = __shfl_sync(0xffffffffu, (y < 32) ? p0 : p1, y & 31);
    if (lane == 0) {
        float wt = (t < L[b]) ? 1.f : 0.f;
        atomicAdd(acc, (lse - py) * wt);
    }
}

__global__ void k_final(const float* __restrict__ acc, float* __restrict__ out, int out_size) {
    if (threadIdx.x == 0) {
        float recon = acc[0] / (float)BT;
        float lat = -0.5f * acc[1] / (float)(NB * LATD);
        if (out_size > 0) out[0] = recon + lat;
        if (out_size > 1) out[1] = recon;
        if (out_size > 2) out[2] = lat;
    }
}

// ---------------- host driver ----------------
extern "C" void kernel_launch(void* const* d_in, const int* in_sizes, int n_in,
                              void* d_out, int out_size) {
    const int*   X       = (const int*)d_in[0];
    const int*   Y       = (const int*)d_in[1];
    const float* C       = (const float*)d_in[2];
    const int*   L       = (const int*)d_in[3];
    const float* eps     = (const float*)d_in[4];
    const float* emb_enc = (const float*)d_in[5];
    const float* emb_dec = (const float*)d_in[6];
    const float* enc_k[3]  = {(const float*)d_in[7],  (const float*)d_in[10], (const float*)d_in[13]};
    const float* enc_rk[3] = {(const float*)d_in[8],  (const float*)d_in[11], (const float*)d_in[14]};
    const float* enc_b[3]  = {(const float*)d_in[9],  (const float*)d_in[12], (const float*)d_in[15]};
    const float* dec_k[3]  = {(const float*)d_in[16], (const float*)d_in[19], (const float*)d_in[22]};
    const float* dec_rk[3] = {(const float*)d_in[17], (const float*)d_in[20], (const float*)d_in[23]};
    const float* dec_b[3]  = {(const float*)d_in[18], (const float*)d_in[21], (const float*)d_in[24]};
    const float* Wm = (const float*)d_in[25];
    const float* bm = (const float*)d_in[26];
    const float* Ws = (const float*)d_in[27];
    const float* bs = (const float*)d_in[28];
    const float* Wo = (const float*)d_in[29];
    const float* bo = (const float*)d_in[30];

    __nv_bfloat16 *bufA, *bufB, *wt;
    unsigned *rkt, *bar;
    float *Zb, *cst, *mo, *lo, *zl, *acc, *h0, *h1, *hf32, *pb;
    cudaGetSymbolAddress((void**)&bufA, g_bufA);
    cudaGetSymbolAddress((void**)&bufB, g_bufB);
    cudaGetSymbolAddress((void**)&wt,   g_wt);
    cudaGetSymbolAddress((void**)&rkt,  g_rkt);
    cudaGetSymbolAddress((void**)&Zb,   g_Z);
    cudaGetSymbolAddress((void**)&cst,  g_c);
    cudaGetSymbolAddress((void**)&mo,   g_mean);
    cudaGetSymbolAddress((void**)&lo,   g_ls);
    cudaGetSymbolAddress((void**)&zl,   g_zlat);
    cudaGetSymbolAddress((void**)&acc,  g_acc);
    cudaGetSymbolAddress((void**)&h0,   g_h0);
    cudaGetSymbolAddress((void**)&h1,   g_h1);
    cudaGetSymbolAddress((void**)&hf32, g_hf32);
    cudaGetSymbolAddress((void**)&pb,   g_pbias);
    cudaGetSymbolAddress((void**)&bar,  g_bar);

    static int smem_set = 0;
    if (!smem_set) {
        cudaFuncSetAttribute(k_scan_tf32, cudaFuncAttributeMaxDynamicSharedMemorySize, SMEM_SCAN);
        cudaFuncSetAttribute(k_gemm_bf16, cudaFuncAttributeMaxDynamicSharedMemorySize, SMEM_GEMM);
        smem_set = 1;
    }

    k_zero<<<1, 64>>>(acc, 2);

    dim3 gemm_grid(G4U / 128, BT / 128);
    dim3 conv_grid(64, 16);
    dim3 scan_grid(32, 4);

    const int encKs[3] = {LATD + PP, UU, UU};
    const int decKs[3] = {2 * LATD + PP, UU, UU};
    const int encMode[3] = {1, 1, 0};
    const int decMode[3] = {1, 1, 2};

    // ======== encoder ========
    k_build_enc<<<BT, 256>>>(X, emb_enc, C, bufA);
    {
        __nv_bfloat16* inb = bufA;
        __nv_bfloat16* outb = bufB;
        for (int l = 0; l < 3; l++) {
            k_convT<<<conv_grid, 256>>>(enc_k[l], encKs[l], wt);
            k_permbias<<<8, 256>>>(enc_b[l], pb);
            k_gemm_bf16<<<gemm_grid, 256, SMEM_GEMM>>>(inb, wt, pb, Zb);
            k_convT_tf32<<<conv_grid, 256>>>(enc_rk[l], rkt);
            k_reset_bar<<<1, 32>>>(bar);
            k_scan_tf32<<<scan_grid, 512, SMEM_SCAN>>>(Zb, rkt, h0, h1, outb, hf32, cst, bar, encMode[l]);
            __nv_bfloat16* tmp = inb; inb = outb; outb = tmp;
        }
    }
    k_mean_ls<<<(NB * LATD + 255) / 256, 256>>>(cst, Wm, bm, Ws, bs, eps, mo, lo, zl);
    k_latent<<<(NB * LATD + 255) / 256, 256>>>(mo, lo, acc);

    // ======== decoder ========
    k_build_dec<<<BT, 256>>>(X, emb_dec, C, zl, bufA);
    {
        __nv_bfloat16* inb = bufA;
        __nv_bfloat16* outb = bufB;
        for (int l = 0; l < 3; l++) {
            k_convT<<<conv_grid, 256>>>(dec_k[l], decKs[l], wt);
            k_permbias<<<8, 256>>>(dec_b[l], pb);
            k_gemm_bf16<<<gemm_grid, 256, SMEM_GEMM>>>(inb, wt, pb, Zb);
            k_convT_tf32<<<conv_grid, 256>>>(dec_rk[l], rkt);
            k_reset_bar<<<1, 32>>>(bar);
            k_scan_tf32<<<scan_grid, 512, SMEM_SCAN>>>(Zb, rkt, h0, h1, outb, hf32, cst, bar, decMode[l]);
            __nv_bfloat16* tmp = inb; inb = outb; outb = tmp;
        }
    }

    // ======== losses ========
    k_ce<<<BT / 8, 256>>>(hf32, Wo, bo, Y, L, acc);
    k_final<<<1, 32>>>(acc, (float*)d_out, out_size);
}

// round 11
// speedup vs baseline: 1.2542x; 1.0003x over previous
#include <cuda_runtime.h>
#include <cuda_bf16.h>
#include <math.h>

#define NB   256
#define NT   128
#define VOC  42
#define LATD 200
#define UU   512
#define PP   3
#define BT   (NB*NT)
#define G4U  2048
#define DOM_BLOCKS 32

// ---------------- device scratch ----------------
__device__ __nv_bfloat16 g_bufA[(size_t)BT*UU];
__device__ __nv_bfloat16 g_bufB[(size_t)BT*UU];
__device__ float g_Z[(size_t)BT*G4U];              // gate-interleaved: [b,t,u,4]
__device__ float g_hf32[(size_t)BT*UU];            // fp32 hseq (for CE)
__device__ __nv_bfloat16 g_wt[(size_t)G4U*UU];     // permuted weight^T bf16
__device__ float g_pbias[G4U];                     // permuted bias
__device__ unsigned g_rkt[(size_t)G4U*UU];         // recurrent W^T tf32, k-permuted
__device__ float g_h0[NB*UU];                      // h ping (k-permuted u layout)
__device__ float g_h1[NB*UU];                      // h pong (k-permuted u layout)
__device__ float g_c[NB*UU];
__device__ float g_mean[NB*LATD];
__device__ float g_ls[NB*LATD];
__device__ float g_zlat[NB*LATD];
__device__ float g_acc[2];
__device__ unsigned g_bar[4];

__device__ __forceinline__ int permcol(int n) { return ((n & 511) << 2) | (n >> 9); }
// k-permutation within 8-groups: logical (lr, lr+4) -> phys (2lr, 2lr+1)
__device__ __forceinline__ int kperm(int k) {
    return (k & ~7) | ((k & 3) << 1) | ((k >> 2) & 1);
}

// ---------------- helpers ----------------
__device__ __forceinline__ unsigned f2tf32(float x) {
    unsigned r;
    asm("cvt.rna.tf32.f32 %0, %1;" : "=r"(r) : "f"(x));
    return r;
}
__device__ __forceinline__ void mma_tf32(float c[4], const unsigned a[4], const unsigned b[2]) {
    asm volatile(
        "mma.sync.aligned.m16n8k8.row.col.f32.tf32.tf32.f32 "
        "{%0,%1,%2,%3}, {%4,%5,%6,%7}, {%8,%9}, {%0,%1,%2,%3};\n"
        : "+f"(c[0]), "+f"(c[1]), "+f"(c[2]), "+f"(c[3])
        : "r"(a[0]), "r"(a[1]), "r"(a[2]), "r"(a[3]), "r"(b[0]), "r"(b[1]));
}
__device__ __forceinline__ void mma_bf16(float c[4], const unsigned a[4], const unsigned b[2]) {
    asm volatile(
        "mma.sync.aligned.m16n8k16.row.col.f32.bf16.bf16.f32 "
        "{%0,%1,%2,%3}, {%4,%5,%6,%7}, {%8,%9}, {%0,%1,%2,%3};\n"
        : "+f"(c[0]), "+f"(c[1]), "+f"(c[2]), "+f"(c[3])
        : "r"(a[0]), "r"(a[1]), "r"(a[2]), "r"(a[3]), "r"(b[0]), "r"(b[1]));
}
__device__ __forceinline__ float sigm(float x) { return 1.f / (1.f + expf(-x)); }

__device__ __forceinline__ void cp16(void* s, const void* g) {
    unsigned sa = (unsigned)__cvta_generic_to_shared(s);
    asm volatile("cp.async.cg.shared.global [%0], [%1], 16;\n" :: "r"(sa), "l"(g));
}
#define CP_COMMIT() asm volatile("cp.async.commit_group;\n")
#define CP_WAIT(n)  asm volatile("cp.async.wait_group %0;\n" :: "n"(n))

// ---------------- utility kernels ----------------
__global__ void k_zero(float* p, int n) {
    int i = blockIdx.x * blockDim.x + threadIdx.x;
    if (i < n) p[i] = 0.f;
}
__global__ void k_reset_bar(unsigned* b) {
    if (threadIdx.x < 4) b[threadIdx.x] = 0u;
}
__global__ void k_permbias(const float* __restrict__ bias, float* __restrict__ pb) {
    int n = blockIdx.x * blockDim.x + threadIdx.x;
    if (n < G4U) pb[permcol(n)] = bias[n];
}

__global__ void k_build_enc(const int* __restrict__ X, const float* __restrict__ emb,
                            const float* __restrict__ C, __nv_bfloat16* __restrict__ out) {
    int bt = blockIdx.x;
    int b = bt / NT;
    __nv_bfloat16* row = out + (size_t)bt * UU;
    int x = X[bt];
    for (int i = threadIdx.x; i < UU; i += blockDim.x) {
        float v = 0.f;
        if (i < LATD) v = emb[x * LATD + i];
        else if (i < LATD + PP) v = C[b * PP + (i - LATD)];
        row[i] = __float2bfloat16_rn(v);
    }
}
__global__ void k_build_dec(const int* __restrict__ X, const float* __restrict__ emb,
                            const float* __restrict__ C, const float* __restrict__ zl,
                            __nv_bfloat16* __restrict__ out) {
    int bt = blockIdx.x;
    int b = bt / NT;
    __nv_bfloat16* row = out + (size_t)bt * UU;
    int x = X[bt];
    for (int i = threadIdx.x; i < UU; i += blockDim.x) {
        float v = 0.f;
        if (i < LATD) v = zl[b * LATD + i];
        else if (i < 2 * LATD) v = emb[x * LATD + (i - LATD)];
        else if (i < 2 * LATD + PP) v = C[b * PP + (i - 2 * LATD)];
        row[i] = __float2bfloat16_rn(v);
    }
}

__global__ void k_convT(const float* __restrict__ W, int K, __nv_bfloat16* __restrict__ Wt) {
    __shared__ float tile[32][33];
    int nb0 = blockIdx.x * 32;
    int kb0 = blockIdx.y * 32;
    for (int i = threadIdx.x; i < 1024; i += blockDim.x) {
        int r = i >> 5, c = i & 31;
        tile[r][c] = (kb0 + r < K) ? W[(size_t)(kb0 + r) * G4U + nb0 + c] : 0.f;
    }
    __syncthreads();
    for (int i = threadIdx.x; i < 1024; i += blockDim.x) {
        int r = i >> 5, c = i & 31;
        Wt[(size_t)permcol(nb0 + r) * UU + kb0 + c] = __float2bfloat16_rn(tile[c][r]);
    }
}

// rk fp32 [512][2048] -> rkt tf32 [2048][kperm(512)]
__global__ void k_convT_tf32(const float* __restrict__ W, unsigned* __restrict__ Wt) {
    __shared__ float tile[32][33];
    int nb0 = blockIdx.x * 32;
    int kb0 = blockIdx.y * 32;
    for (int i = threadIdx.x; i < 1024; i += blockDim.x) {
        int r = i >> 5, c = i & 31;
        tile[r][c] = W[(size_t)(kb0 + r) * G4U + nb0 + c];
    }
    __syncthreads();
    for (int i = threadIdx.x; i < 1024; i += blockDim.x) {
        int r = i >> 5, c = i & 31;
        Wt[(size_t)(nb0 + r) * UU + kb0 + kperm(c)] = f2tf32(tile[c][r]);
    }
}

// ---------------- big GEMM, cp.async double-buffered ----------------
#define GS (128 * 72)
#define SMEM_GEMM (4 * GS * 2)

__global__ __launch_bounds__(256) void k_gemm_bf16(
    const __nv_bfloat16* __restrict__ A, const __nv_bfloat16* __restrict__ Wt,
    const float* __restrict__ bias, float* __restrict__ Co) {
    extern __shared__ __nv_bfloat16 gsm[];
    int tid = threadIdx.x;
    int wid = tid >> 5, lane = tid & 31;
    int wm = wid >> 1, wn = wid & 1;
    int lq = lane >> 2, lr = lane & 3;
    int row0 = blockIdx.y * 128, col0 = blockIdx.x * 128;

    float c[2][8][4];
#pragma unroll
    for (int mt = 0; mt < 2; mt++)
#pragma unroll
        for (int nt = 0; nt < 8; nt++)
#pragma unroll
            for (int j = 0; j < 4; j++) c[mt][nt][j] = 0.f;

    auto load_chunk = [&](int buf, int kk) {
        __nv_bfloat16* As_ = gsm + buf * 2 * GS;
        __nv_bfloat16* Bs_ = As_ + GS;
#pragma unroll
        for (int j = 0; j < 4; j++) {
            int i = tid + j * 256;
            int r = i >> 3, c8 = (i & 7) * 8;
            cp16(&As_[r * 72 + c8], &A[(size_t)(row0 + r) * UU + kk + c8]);
            cp16(&Bs_[r * 72 + c8], &Wt[(size_t)(col0 + r) * UU + kk + c8]);
        }
    };

    load_chunk(0, 0);
    CP_COMMIT();

    for (int kc = 0; kc < 8; kc++) {
        if (kc < 7) {
            load_chunk((kc + 1) & 1, (kc + 1) * 64);
            CP_COMMIT();
            CP_WAIT(1);
        } else {
            CP_WAIT(0);
        }
        __syncthreads();
        const __nv_bfloat16* As_ = gsm + (kc & 1) * 2 * GS;
        const __nv_bfloat16* Bs_ = As_ + GS;
#pragma unroll
        for (int ks = 0; ks < 4; ks++) {
            int kb = ks * 16;
            unsigned af[2][4];
#pragma unroll
            for (int mt = 0; mt < 2; mt++) {
                int mb = wm * 32 + mt * 16;
                af[mt][0] = *(const unsigned*)&As_[(mb + lq) * 72 + kb + 2 * lr];
                af[mt][1] = *(const unsigned*)&As_[(mb + lq + 8) * 72 + kb + 2 * lr];
                af[mt][2] = *(const unsigned*)&As_[(mb + lq) * 72 + kb + 8 + 2 * lr];
                af[mt][3] = *(const unsigned*)&As_[(mb + lq + 8) * 72 + kb + 8 + 2 * lr];
            }
#pragma unroll
            for (int nt = 0; nt < 8; nt++) {
                int nb = wn * 64 + nt * 8;
                unsigned bf[2];
                bf[0] = *(const unsigned*)&Bs_[(nb + lq) * 72 + kb + 2 * lr];
                bf[1] = *(const unsigned*)&Bs_[(nb + lq) * 72 + kb + 8 + 2 * lr];
#pragma unroll
                for (int mt = 0; mt < 2; mt++) mma_bf16(c[mt][nt], af[mt], bf);
            }
        }
        __syncthreads();
    }
#pragma unroll
    for (int mt = 0; mt < 2; mt++) {
        size_t rb = (size_t)(row0 + wm * 32 + mt * 16 + lq);
#pragma unroll
        for (int nt = 0; nt < 8; nt++) {
            int cb = col0 + wn * 64 + nt * 8 + 2 * lr;
            float b0 = bias[cb], b1 = bias[cb + 1];
            Co[rb * G4U + cb]           = c[mt][nt][0] + b0;
            Co[rb * G4U + cb + 1]       = c[mt][nt][1] + b1;
            Co[(rb + 8) * G4U + cb]     = c[mt][nt][2] + b0;
            Co[(rb + 8) * G4U + cb + 1] = c[mt][nt][3] + b1;
        }
    }
}

// ---------------- persistent tf32 scan: operand-swapped, LDS.64 fragments ----------------
// A = rk slice (Wsm, m=64 gate-cols), B = h (hsm, n=64 batches), both k-permuted.
// 512 threads = 16 warps: kt(2 k-teams) x wm(2 gate-halves of 32) x wn(4 batch-quarters of 16).
#define SC_WS 520
#define SC_HS 136
#define SMEM_SCAN (64*SC_WS*4 + 2*64*SC_HS*4 + 64*68*4 + 64*16*4)

__global__ __launch_bounds__(512) void k_scan_tf32(
    const float* __restrict__ Z, const unsigned* __restrict__ rkt,
    float* __restrict__ h0buf, float* __restrict__ h1buf,
    __nv_bfloat16* __restrict__ hseq, float* __restrict__ hseq32,
    float* __restrict__ cfin, volatile unsigned* bar, int mode) {
    extern __shared__ char smraw[];
    unsigned* Wsm = (unsigned*)smraw;                                   // [64][520]
    float* hsm0 = (float*)(smraw + 64 * SC_WS * 4);                     // [64][136]
    float* hsm1 = hsm0 + 64 * SC_HS;
    float* zsm = (float*)(smraw + 64 * SC_WS * 4 + 2 * 64 * SC_HS * 4); // [64][68]
    float* csm = zsm + 64 * 68;                                          // [64][16]

    int tid = threadIdx.x;
    int wid = tid >> 5, lane = tid & 31;
    int kt = wid & 1;                 // k-team
    int wm = (wid >> 1) & 1;          // gate-half (32 gate-cols)
    int wn = wid >> 2;                // batch-quarter (16 batches), 0..3
    int lq = lane >> 2, lr = lane & 3;
    int u0 = blockIdx.x * 16;
    int b0 = blockIdx.y * 64;
    volatile unsigned* mybar = bar + blockIdx.y;

    // load rk slice once (rows = gatecol g = gate*16+ulocal; k already permuted)
    for (int i = tid; i < 64 * 128; i += 512) {
        int nl = i >> 7, kq = (i & 127) * 4;
        int n = (nl >> 4) * 512 + u0 + (nl & 15);
        *(uint4*)&Wsm[nl * SC_WS + kq] = *(const uint4*)&rkt[(size_t)n * UU + kq];
    }
    for (int i = tid; i < 1024; i += 512) csm[i] = 0.f;
    for (int i = tid; i < 64 * 68; i += 512) zsm[i] = 0.f;
    __syncthreads();

    for (int t = 0; t < NT; t++) {
        float4 zreg[2];
#pragma unroll
        for (int rep = 0; rep < 2; rep++) {
            int e = rep * 512 + tid;
            int bl = e >> 4, ulx = e & 15;
            zreg[rep] = __ldg((const float4*)&Z[(((size_t)(b0 + bl) * NT + t) << 11) +
                                                ((u0 + ulx) << 2)]);
        }

        float acc[2][2][4];   // [mt][nt][4]
#pragma unroll
        for (int mt = 0; mt < 2; mt++)
#pragma unroll
            for (int nt = 0; nt < 2; nt++)
#pragma unroll
                for (int j = 0; j < 4; j++) acc[mt][nt][j] = 0.f;

        if (t > 0) {
            if (tid == 0) {
                unsigned target = (unsigned)t * DOM_BLOCKS;
                while (*mybar < target) {}
            }
            __syncthreads();
            const float* hprev = ((t - 1) & 1) ? h1buf : h0buf;

#pragma unroll
            for (int j = 0; j < 4; j++) {
                int i = tid + j * 512;
                int r = i >> 5, cq = (i & 31) * 4;
                cp16(&hsm0[r * SC_HS + cq], &hprev[(size_t)(b0 + r) * UU + cq]);
            }
            CP_COMMIT();

            int mb = wm * 32;
            int nbw = wn * 16;
            for (int kc = 0; kc < 4; kc++) {
                float* cur = (kc & 1) ? hsm1 : hsm0;
                float* nxt = (kc & 1) ? hsm0 : hsm1;
                if (kc < 3) {
                    int kk = (kc + 1) * 128;
#pragma unroll
                    for (int j = 0; j < 4; j++) {
                        int i = tid + j * 512;
                        int r = i >> 5, cq = (i & 31) * 4;
                        cp16(&nxt[r * SC_HS + cq], &hprev[(size_t)(b0 + r) * UU + kk + cq]);
                    }
                    CP_COMMIT();
                    CP_WAIT(1);
                } else {
                    CP_WAIT(0);
                }
                __syncthreads();
                const unsigned* cu = (const unsigned*)cur;
#pragma unroll
                for (int ks = 0; ks < 8; ks++) {
                    int kb = kc * 128 + (kt * 8 + ks) * 8 + 2 * lr;
                    unsigned af[2][4];
#pragma unroll
                    for (int mt = 0; mt < 2; mt++) {
                        int row = mb + mt * 16;
                        uint2 p = *(const uint2*)&Wsm[(row + lq) * SC_WS + kb];
                        uint2 q = *(const uint2*)&Wsm[(row + lq + 8) * SC_WS + kb];
                        af[mt][0] = p.x; af[mt][2] = p.y;
                        af[mt][1] = q.x; af[mt][3] = q.y;
                    }
                    int kbh = (kt * 8 + ks) * 8 + 2 * lr;
#pragma unroll
                    for (int nt = 0; nt < 2; nt++) {
                        uint2 r2 = *(const uint2*)&cu[(nbw + nt * 8 + lq) * SC_HS + kbh];
                        unsigned bf[2] = {r2.x, r2.y};
#pragma unroll
                        for (int mt = 0; mt < 2; mt++) mma_tf32(acc[mt][nt], af[mt], bf);
                    }
                }
                __syncthreads();
            }

            // merge k-teams: scatter D(m=gate, n=batch) into zsm[batch][gate]
#pragma unroll
            for (int mt = 0; mt < 2; mt++) {
                int g0 = mb + mt * 16 + lq;
#pragma unroll
                for (int nt = 0; nt < 2; nt++) {
                    int bl = nbw + nt * 8 + 2 * lr;
                    atomicAdd(&zsm[bl * 68 + g0],           acc[mt][nt][0]);
                    atomicAdd(&zsm[(bl + 1) * 68 + g0],     acc[mt][nt][1]);
                    atomicAdd(&zsm[bl * 68 + g0 + 8],       acc[mt][nt][2]);
                    atomicAdd(&zsm[(bl + 1) * 68 + g0 + 8], acc[mt][nt][3]);
                }
            }
        }
        __syncthreads();

        // LSTM update: 64b x 16u, 2 outputs/thread; zero zsm in-place after read
        float* hnext = (t & 1) ? h1buf : h0buf;
#pragma unroll
        for (int rep = 0; rep < 2; rep++) {
            int e = rep * 512 + tid;
            int bl = e >> 4, ulx = e & 15;
            int b = b0 + bl, u = u0 + ulx;
            float zi = zsm[bl * 68 + ulx]      + zreg[rep].x;
            float zf = zsm[bl * 68 + 16 + ulx] + zreg[rep].y;
            float zg = zsm[bl * 68 + 32 + ulx] + zreg[rep].z;
            float zo = zsm[bl * 68 + 48 + ulx] + zreg[rep].w;
            zsm[bl * 68 + ulx] = 0.f;
            zsm[bl * 68 + 16 + ulx] = 0.f;
            zsm[bl * 68 + 32 + ulx] = 0.f;
            zsm[bl * 68 + 48 + ulx] = 0.f;
            float co = csm[bl * 16 + ulx];
            float c2 = sigm(zf) * co + sigm(zi) * tanhf(zg);
            float h2 = sigm(zo) * tanhf(c2);
            csm[bl * 16 + ulx] = c2;
            // store h rounded-to-tf32, at k-permuted u position
            int up = u0 + ((ulx & 8) | ((ulx & 3) << 1) | ((ulx >> 2) & 1));
            __stcg(&hnext[(size_t)b * UU + up], __uint_as_float(f2tf32(h2)));
            size_t so = ((size_t)b * NT + t) * UU + u;
            if (mode & 1) hseq[so] = __float2bfloat16_rn(h2);
            if (mode & 2) hseq32[so] = h2;
        }

        if (t < NT - 1) {
            __threadfence();
            __syncthreads();
            if (tid == 0) atomicAdd((unsigned*)mybar, 1u);
        }
    }
#pragma unroll
    for (int rep = 0; rep < 2; rep++) {
        int e = rep * 512 + tid;
        int bl = e >> 4, ulx = e & 15;
        cfin[(b0 + bl) * UU + u0 + ulx] = csm[bl * 16 + ulx];
    }
}

// ---------------- mean / log_sigma / reparameterize ----------------
__global__ void k_mean_ls(const float* __restrict__ cst,
                          const float* __restrict__ Wm, const float* __restrict__ bm,
                          const float* __restrict__ Ws, const float* __restrict__ bs,
                          const float* __restrict__ eps,
                          float* __restrict__ mo, float* __restrict__ lo, float* __restrict__ zo) {
    int idx = blockIdx.x * blockDim.x + threadIdx.x;
    if (idx >= NB * LATD) return;
    int b = idx / LATD, l = idx % LATD;
    const float* cr = cst + b * UU;
    float m = bm[l], s = bs[l];
    for (int k = 0; k < UU; k++) {
        float cv = cr[k];
        m += cv * Wm[k * LATD + l];
        s += cv * Ws[k * LATD + l];
    }
    mo[idx] = m;
    lo[idx] = s;
    zo[idx] = m + expf(0.5f * s) * eps[idx];
}

__global__ void k_latent(const float* __restrict__ mo, const float* __restrict__ lo,
                         float* __restrict__ acc) {
    __shared__ float sdata[256];
    int idx = blockIdx.x * blockDim.x + threadIdx.x;
    float v = 0.f;
    if (idx < NB * LATD) {
        float m = mo[idx], s = lo[idx];
        v = 1.f + s - m * m - expf(s);
    }
    sdata[threadIdx.x] = v;
    __syncthreads();
    for (int o = 128; o > 0; o >>= 1) {
        if (threadIdx.x < o) sdata[threadIdx.x] += sdata[threadIdx.x + o];
        __syncthreads();
    }
    if (threadIdx.x == 0) atomicAdd(acc + 1, sdata[0]);
}

// ---------------- fused logits + log-softmax + masked CE (fp32 h) ----------------
__global__ void k_ce(const float* __restrict__ H, const float* __restrict__ Wo,
                     const float* __restrict__ bo, const int* __restrict__ Y,
                     const int* __restrict__ L, float* __restrict__ acc) {
    __shared__ float hs[8][UU];
    int row0 = blockIdx.x * 8;
    for (int i = threadIdx.x; i < 8 * UU; i += 256) {
        int r = i >> 9, k = i & 511;
        hs[r][k] = H[(size_t)(row0 + r) * UU + k];
    }
    __syncthreads();
    int w = threadIdx.x >> 5, lane = threadIdx.x & 31;
    int row = row0 + w;
    int b = row / NT, t = row % NT;

    float d0 = 0.f, d1 = 0.f;
    bool has1 = (lane + 32) < VOC;
    for (int k = 0; k < UU; k++) {
        float hv = hs[w][k];
        d0 += hv * Wo[k * VOC + lane];
        if (has1) d1 += hv * Wo[k * VOC + lane + 32];
    }
    float p0 = d0 + bo[lane];
    float p1 = has1 ? (d1 + bo[lane + 32]) : -1e30f;
    float m = fmaxf(p0, p1);
#pragma unroll
    for (int o = 16; o; o >>= 1) m = fmaxf(m, __shfl_xor_sync(0xffffffffu, m, o));
    float e = expf(p0 - m) + (has1 ? expf(p1 - m) : 0.f);
#pragma unroll
    for (int o = 16; o; o >>= 1) e += __shfl_xor_sync(0xffffffffu, e, o);
    float lse = logf(e) + m;
    int y = Y[row];
    float py = __shfl_sync(0xffffffffu, (y < 32) ? p0 : p1, y & 31);
    if (lane == 0) {
        float wt = (t < L[b]) ? 1.f : 0.f;
        atomicAdd(acc, (lse - py) * wt);
    }
}

__global__ void k_final(const float* __restrict__ acc, float* __restrict__ out, int out_size) {
    if (threadIdx.x == 0) {
        float recon = acc[0] / (float)BT;
        float lat = -0.5f * acc[1] / (float)(NB * LATD);
        if (out_size > 0) out[0] = recon + lat;
        if (out_size > 1) out[1] = recon;
        if (out_size > 2) out[2] = lat;
    }
}

// ---------------- host driver ----------------
extern "C" void kernel_launch(void* const* d_in, const int* in_sizes, int n_in,
                              void* d_out, int out_size) {
    const int*   X       = (const int*)d_in[0];
    const int*   Y       = (const int*)d_in[1];
    const float* C       = (const float*)d_in[2];
    const int*   L       = (const int*)d_in[3];
    const float* eps     = (const float*)d_in[4];
    const float* emb_enc = (const float*)d_in[5];
    const float* emb_dec = (const float*)d_in[6];
    const float* enc_k[3]  = {(const float*)d_in[7],  (const float*)d_in[10], (const float*)d_in[13]};
    const float* enc_rk[3] = {(const float*)d_in[8],  (const float*)d_in[11], (const float*)d_in[14]};
    const float* enc_b[3]  = {(const float*)d_in[9],  (const float*)d_in[12], (const float*)d_in[15]};
    const float* dec_k[3]  = {(const float*)d_in[16], (const float*)d_in[19], (const float*)d_in[22]};
    const float* dec_rk[3] = {(const float*)d_in[17], (const float*)d_in[20], (const float*)d_in[23]};
    const float* dec_b[3]  = {(const float*)d_in[18], (const float*)d_in[21], (const float*)d_in[24]};
    const float* Wm = (const float*)d_in[25];
    const float* bm = (const float*)d_in[26];
    const float* Ws = (const float*)d_in[27];
    const float* bs = (const float*)d_in[28];
    const float* Wo = (const float*)d_in[29];
    const float* bo = (const float*)d_in[30];

    __nv_bfloat16 *bufA, *bufB, *wt;
    unsigned *rkt, *bar;
    float *Zb, *cst, *mo, *lo, *zl, *acc, *h0, *h1, *hf32, *pb;
    cudaGetSymbolAddress((void**)&bufA, g_bufA);
    cudaGetSymbolAddress((void**)&bufB, g_bufB);
    cudaGetSymbolAddress((void**)&wt,   g_wt);
    cudaGetSymbolAddress((void**)&rkt,  g_rkt);
    cudaGetSymbolAddress((void**)&Zb,   g_Z);
    cudaGetSymbolAddress((void**)&cst,  g_c);
    cudaGetSymbolAddress((void**)&mo,   g_mean);
    cudaGetSymbolAddress((void**)&lo,   g_ls);
    cudaGetSymbolAddress((void**)&zl,   g_zlat);
    cudaGetSymbolAddress((void**)&acc,  g_acc);
    cudaGetSymbolAddress((void**)&h0,   g_h0);
    cudaGetSymbolAddress((void**)&h1,   g_h1);
    cudaGetSymbolAddress((void**)&hf32, g_hf32);
    cudaGetSymbolAddress((void**)&pb,   g_pbias);
    cudaGetSymbolAddress((void**)&bar,  g_bar);

    static int smem_set = 0;
    if (!smem_set) {
        cudaFuncSetAttribute(k_scan_tf32, cudaFuncAttributeMaxDynamicSharedMemorySize, SMEM_SCAN);
        cudaFuncSetAttribute(k_gemm_bf16, cudaFuncAttributeMaxDynamicSharedMemorySize, SMEM_GEMM);
        smem_set = 1;
    }

    k_zero<<<1, 64>>>(acc, 2);

    dim3 gemm_grid(G4U / 128, BT / 128);
    dim3 conv_grid(64, 16);
    dim3 scan_grid(32, 4);

    const int encKs[3] = {LATD + PP, UU, UU};
    const int decKs[3] = {2 * LATD + PP, UU, UU};
    const int encMode[3] = {1, 1, 0};
    const int decMode[3] = {1, 1, 2};

    // ======== encoder ========
    k_build_enc<<<BT, 256>>>(X, emb_enc, C, bufA);
    {
        __nv_bfloat16* inb = bufA;
        __nv_bfloat16* outb = bufB;
        for (int l = 0; l < 3; l++) {
            k_convT<<<conv_grid, 256>>>(enc_k[l], encKs[l], wt);
            k_permbias<<<8, 256>>>(enc_b[l], pb);
            k_gemm_bf16<<<gemm_grid, 256, SMEM_GEMM>>>(inb, wt, pb, Zb);
            k_convT_tf32<<<conv_grid, 256>>>(enc_rk[l], rkt);
            k_reset_bar<<<1, 32>>>(bar);
            k_scan_tf32<<<scan_grid, 512, SMEM_SCAN>>>(Zb, rkt, h0, h1, outb, hf32, cst, bar, encMode[l]);
            __nv_bfloat16* tmp = inb; inb = outb; outb = tmp;
        }
    }
    k_mean_ls<<<(NB * LATD + 255) / 256, 256>>>(cst, Wm, bm, Ws, bs, eps, mo, lo, zl);
    k_latent<<<(NB * LATD + 255) / 256, 256>>>(mo, lo, acc);

    // ======== decoder ========
    k_build_dec<<<BT, 256>>>(X, emb_dec, C, zl, bufA);
    {
        __nv_bfloat16* inb = bufA;
        __nv_bfloat16* outb = bufB;
        for (int l = 0; l < 3; l++) {
            k_convT<<<conv_grid, 256>>>(dec_k[l], decKs[l], wt);
            k_permbias<<<8, 256>>>(dec_b[l], pb);
            k_gemm_bf16<<<gemm_grid, 256, SMEM_GEMM>>>(inb, wt, pb, Zb);
            k_convT_tf32<<<conv_grid, 256>>>(dec_rk[l], rkt);
            k_reset_bar<<<1, 32>>>(bar);
            k_scan_tf32<<<scan_grid, 512, SMEM_SCAN>>>(Zb, rkt, h0, h1, outb, hf32, cst, bar, decMode[l]);
            __nv_bfloat16* tmp = inb; inb = outb; outb = tmp;
        }
    }

    // ======== losses ========
    k_ce<<<BT / 8, 256>>>(hf32, Wo, bo, Y, L, acc);
    k_final<<<1, 32>>>(acc, (float*)d_out, out_size);
}